// round 12
// baseline (speedup 1.0000x reference)
#include <cuda_runtime.h>
#include <cuda_fp16.h>
#include <math.h>
#include <stdint.h>

#define BB 2
#define SS 2048
#define DIMM 2048
#define NH 16
#define QR 1536
#define KVR 512
#define DN 128
#define DR 64
#define DVV 128
#define MT (BB*SS)   // 4096 token rows

#define NDOWN 2112   // qc(1536) | kvc(512) | kr(64)
#define NDOWNP 2176  // 17 * 128
#define NUP 3072     // qn(2048) | qp(1024)

// ---------------- fp32 scratch ----------------
__device__ float g_dall[MT*NDOWN];
__device__ float g_qnp [MT*NUP];
__device__ float g_kvup[MT*NH*(DN+DVV)];

// ---------------- fp16 scratch ----------------
__device__ __half g_xs   [MT    * 2*DIMM];
__device__ __half g_wdall[NDOWNP* DIMM];
__device__ __half g_qcs  [MT    * 2*QR];
__device__ __half g_wuall[NUP   * QR];
__device__ __half g_kvcs [MT    * 2*KVR];
__device__ __half g_wkvu [(NH*(DN+DVV)) * KVR];
__device__ __half g_ats  [MT    * (NH*DVV)];
__device__ __half g_wos  [DIMM  * (NH*DVV)];

// ---------------- attention packed operands ----------------
__device__ __half g_qsp[BB*NH*SS*384];     // [bh][s][Qh(192)|Ql(192)]
__device__ __half g_ksp[BB*NH*SS*192];     // [bh][s][Kh(192)]
__device__ __half g_vt [BB*NH*128*SS];     // [bh][d][s]

// ============================================================
// helpers
// ============================================================
__device__ __forceinline__ uint32_t smem_u32(const void* p){
    uint32_t a;
    asm("{ .reg .u64 t; cvta.to.shared.u64 t, %1; cvt.u32.u64 %0, t; }" : "=r"(a) : "l"(p));
    return a;
}
#define CPA16(dst, src) asm volatile("cp.async.cg.shared.global [%0], [%1], 16;" :: "r"(dst), "l"(src))
#define CPCOMMIT()      asm volatile("cp.async.commit_group;")
#define CPWAIT(n)       asm volatile("cp.async.wait_group %0;" :: "n"(n))

__device__ __forceinline__ void ldsm4(uint32_t* r, uint32_t addr){
    asm volatile("ldmatrix.sync.aligned.m8n8.x4.shared.b16 {%0,%1,%2,%3}, [%4];"
        : "=r"(r[0]), "=r"(r[1]), "=r"(r[2]), "=r"(r[3]) : "r"(addr));
}
__device__ __forceinline__ void mma16816(float* c, const uint32_t* a, uint32_t b0, uint32_t b1){
    asm volatile("mma.sync.aligned.m16n8k16.row.col.f32.f16.f16.f32 "
        "{%0,%1,%2,%3}, {%4,%5,%6,%7}, {%8,%9}, {%0,%1,%2,%3};"
        : "+f"(c[0]), "+f"(c[1]), "+f"(c[2]), "+f"(c[3])
        : "r"(a[0]), "r"(a[1]), "r"(a[2]), "r"(a[3]), "r"(b0), "r"(b1));
}
__device__ __forceinline__ uint32_t sw128(int row, int chunk){
    return (uint32_t)(row * 128 + ((chunk ^ (row & 7)) * 16));
}
__device__ __forceinline__ void split8(const float* v, __half* hi, __half* lo){
#pragma unroll
    for (int k = 0; k < 8; k++) {
        __half h = __float2half(v[k]);
        hi[k] = h;
        lo[k] = __float2half(v[k] - __half2float(h));
    }
}

// ============================================================
// vectorized conversions (R10, verified)
// ============================================================
__global__ void splitA_k(const float* __restrict__ in, __half* __restrict__ out,
                         int R, int Rpad, int C, int inPitch)
{
    long long i = (long long)blockIdx.x * blockDim.x + threadIdx.x;
    int C8 = C >> 3;
    long long tot = (long long)Rpad * C8;
    if (i >= tot) return;
    int r = (int)(i / C8), c = ((int)(i % C8)) << 3;
    float v[8];
    if (r < R) {
        float4 a = *(const float4*)&in[(size_t)r * inPitch + c];
        float4 b = *(const float4*)&in[(size_t)r * inPitch + c + 4];
        v[0]=a.x; v[1]=a.y; v[2]=a.z; v[3]=a.w; v[4]=b.x; v[5]=b.y; v[6]=b.z; v[7]=b.w;
    } else {
#pragma unroll
        for (int k = 0; k < 8; k++) v[k] = 0.f;
    }
    __align__(16) __half hi[8], lo[8];
    split8(v, hi, lo);
    size_t base = (size_t)r * 2 * C;
    *(uint4*)&out[base + c]     = *(uint4*)hi;
    *(uint4*)&out[base + C + c] = *(uint4*)lo;
}

__global__ void cvtB_k(const float* __restrict__ in, __half* __restrict__ out,
                       int R, int Rpad, int C, int inPitch)
{
    long long i = (long long)blockIdx.x * blockDim.x + threadIdx.x;
    int C8 = C >> 3;
    long long tot = (long long)Rpad * C8;
    if (i >= tot) return;
    int r = (int)(i / C8), c = ((int)(i % C8)) << 3;
    __align__(16) __half h[8];
    if (r < R) {
        float4 a = *(const float4*)&in[(size_t)r * inPitch + c];
        float4 b = *(const float4*)&in[(size_t)r * inPitch + c + 4];
        h[0]=__float2half(a.x); h[1]=__float2half(a.y); h[2]=__float2half(a.z); h[3]=__float2half(a.w);
        h[4]=__float2half(b.x); h[5]=__float2half(b.y); h[6]=__float2half(b.z); h[7]=__float2half(b.w);
    } else {
#pragma unroll
        for (int k = 0; k < 8; k++) h[k] = __float2half(0.f);
    }
    *(uint4*)&out[(size_t)r * C + c] = *(uint4*)h;
}

// ============================================================
// fp16 GEMM — 256x128 CTA tile, 64x64 warp tiles (LDSM-traffic halved)
// A [hi|lo] pitch KA; B hi pitch K; KA=2K 2-term, KA=K 1-term.
// ============================================================
#define STAGES 3
#define ASTG 32768
#define BSTG 16384
#define STG_BYTES (ASTG+BSTG)
#define GEMM_SMEM (STAGES*STG_BYTES)   // 147456

__global__ __launch_bounds__(256, 1) void gemm_tc(
    const __half* __restrict__ A, const __half* __restrict__ B,
    float* __restrict__ C, int M, int N, int K, int KA)
{
    extern __shared__ __align__(16) char smem[];
    const uint32_t sb = smem_u32(smem);
    const int m0 = blockIdx.y * 256, n0 = blockIdx.x * 128;
    const int tid = threadIdx.x, lane = tid & 31;
    const int wm = (tid >> 5) & 3;      // 0..3 -> 64-row slice
    const int wn = tid >> 7;            // 0..1 -> 64-col slice

    float acc[4][8][4];
#pragma unroll
    for (int i = 0; i < 4; i++)
#pragma unroll
        for (int j = 0; j < 8; j++)
#pragma unroll
            for (int q = 0; q < 4; q++) acc[i][j][q] = 0.f;

    const int KT  = KA >> 6;
    const int KTh = K >> 6;
    const __half* Ag0 = A + (size_t)m0 * KA;
    const __half* Bg0 = B + (size_t)n0 * K;

    const int fr = tid >> 3;   // 0..31
    const int fc = tid & 7;

    auto fill = [&](int j){
        uint32_t base = sb + (uint32_t)(j % STAGES) * STG_BYTES;
        int ka = j << 6;
        int kb = (j >= KTh ? j - KTh : j) << 6;
#pragma unroll
        for (int i = 0; i < 8; i++) {               // A: 256 rows
            int r = fr + i * 32;
            CPA16(base + sw128(r, fc), Ag0 + (size_t)r * KA + ka + fc*8);
        }
#pragma unroll
        for (int i = 0; i < 4; i++) {               // B: 128 rows
            int r = fr + i * 32;
            CPA16(base + ASTG + sw128(r, fc), Bg0 + (size_t)r * K + kb + fc*8);
        }
        CPCOMMIT();
    };

    fill(0);
    fill(1);

    const int a_row  = lane & 15;
    const int a_ch   = lane >> 4;
    const int b_nrow = (lane & 7) + ((lane & 16) ? 8 : 0);
    const int b_ch   = (lane >> 3) & 1;

    for (int kt = 0; kt < KT; kt++) {
        CPWAIT(1);
        __syncthreads();
        if (kt + 2 < KT) fill(kt + 2);
        else CPCOMMIT();

        uint32_t aT = sb + (uint32_t)(kt % STAGES) * STG_BYTES;
        uint32_t bT = aT + ASTG;
#pragma unroll
        for (int ks = 0; ks < 4; ks++) {
            uint32_t a[4][4];
#pragma unroll
            for (int i = 0; i < 4; i++)
                ldsm4(a[i], aT + sw128(wm*64 + i*16 + a_row, ks*2 + a_ch));
            uint32_t b[4][4];
#pragma unroll
            for (int g = 0; g < 4; g++)
                ldsm4(b[g], bT + sw128(wn*64 + g*16 + b_nrow, ks*2 + b_ch));
#pragma unroll
            for (int i = 0; i < 4; i++)
#pragma unroll
                for (int g = 0; g < 4; g++) {
                    mma16816(acc[i][2*g],   a[i], b[g][0], b[g][1]);
                    mma16816(acc[i][2*g+1], a[i], b[g][2], b[g][3]);
                }
        }
    }

    const int rb = m0 + wm*64;
    const int cb = n0 + wn*64;
#pragma unroll
    for (int i = 0; i < 4; i++)
#pragma unroll
        for (int j = 0; j < 8; j++) {
            int c = cb + j*8 + (lane & 3)*2;
            if (c < N) {
                int r = rb + i*16 + (lane >> 2);
                *(float2*)&C[(size_t)r * N + c]     = make_float2(acc[i][j][0], acc[i][j][1]);
                *(float2*)&C[(size_t)(r+8) * N + c] = make_float2(acc[i][j][2], acc[i][j][3]);
            }
        }
}

// ---------------- RMSNorm -> split fp16 (R10, verified) ----------------
__global__ void rmsnorm_split_k(const float* __restrict__ x, const float* __restrict__ w,
                                __half* __restrict__ out, int W, int pitch)
{
    const int row = blockIdx.x;
    const float* xr = x + (size_t)row * pitch;
    const float4* x4 = (const float4*)xr;
    float ss = 0.f;
    int W4 = W >> 2;
    for (int i = threadIdx.x; i < W4; i += blockDim.x) {
        float4 v = x4[i];
        ss += v.x*v.x + v.y*v.y + v.z*v.z + v.w*v.w;
    }
    __shared__ float red[32];
#pragma unroll
    for (int o = 16; o; o >>= 1) ss += __shfl_down_sync(0xffffffffu, ss, o);
    if ((threadIdx.x & 31) == 0) red[threadIdx.x >> 5] = ss;
    __syncthreads();
    if (threadIdx.x < 32) {
        float v = (threadIdx.x < (blockDim.x >> 5)) ? red[threadIdx.x] : 0.f;
#pragma unroll
        for (int o = 16; o; o >>= 1) v += __shfl_down_sync(0xffffffffu, v, o);
        if (threadIdx.x == 0) red[0] = rsqrtf(v / (float)W + 1e-6f);
    }
    __syncthreads();
    float r = red[0];
    __half* orow = out + (size_t)row * 2 * W;
    const float4* w4 = (const float4*)w;
    int W8 = W >> 3;
    for (int i8 = threadIdx.x; i8 < W8; i8 += blockDim.x) {
        float4 a = x4[i8*2], b = x4[i8*2+1];
        float4 wa = w4[i8*2], wb = w4[i8*2+1];
        float v[8] = { a.x*r*wa.x, a.y*r*wa.y, a.z*r*wa.z, a.w*r*wa.w,
                       b.x*r*wb.x, b.y*r*wb.y, b.z*r*wb.z, b.w*r*wb.w };
        __align__(16) __half hi[8], lo[8];
        split8(v, hi, lo);
        *(uint4*)&orow[i8*8]     = *(uint4*)hi;
        *(uint4*)&orow[W + i8*8] = *(uint4*)lo;
    }
}

// ---------------- RoPE on k_rope slice of dall ----------------
__global__ void rope_k(float* __restrict__ x, int pitch, int colOff,
                       int nheads, int d, int total_pairs)
{
    int idx = blockIdx.x * blockDim.x + threadIdx.x;
    if (idx >= total_pairs) return;
    int pairs_per_row = nheads * (d / 2);
    int row = idx / pairs_per_row;
    int p   = idx % pairs_per_row;
    int h = p / (d / 2);
    int i = p % (d / 2);
    int pos = row % SS;
    float inv = powf(10000.f, (-2.0f * (float)i) / (float)d);
    float ang = (float)pos * inv;
    float s, c;
    sincosf(ang, &s, &c);
    float* base = x + (size_t)row * pitch + colOff + h * d + 2 * i;
    float x1 = base[0], x2 = base[1];
    base[0] = x1 * c - x2 * s;
    base[1] = x1 * s + x2 * c;
}

// ---------------- fused Q rope + split pack (R10, verified) ----------------
__global__ void rope_pack_q(const float* __restrict__ qnp, __half* __restrict__ out)
{
    long long idx = (long long)blockIdx.x * blockDim.x + threadIdx.x;
    if (idx >= (long long)BB*NH*SS*24) return;
    int c8 = (int)(idx % 24);
    int s  = (int)((idx / 24) % SS);
    int bh = (int)(idx / (24LL*SS));
    int b = bh / NH, h = bh % NH;
    size_t m = (size_t)b * SS + s;
    const float scale = 0.072168783648703220563f;
    size_t base = ((size_t)bh * SS + s) * 384;
    int d = c8 * 8;
    float v[8];
    if (c8 < 16) {
        const float4* src = (const float4*)&qnp[m * NUP + h*128 + d];
        float4 a = src[0], bb = src[1];
        v[0]=a.x; v[1]=a.y; v[2]=a.z; v[3]=a.w; v[4]=bb.x; v[5]=bb.y; v[6]=bb.z; v[7]=bb.w;
#pragma unroll
        for (int k = 0; k < 8; k++) v[k] *= scale;
    } else {
        int r8 = c8 - 16;
        const float4* src = (const float4*)&qnp[m * NUP + 2048 + h*64 + r8*8];
        float4 a = src[0], bb = src[1];
        float t[8] = {a.x, a.y, a.z, a.w, bb.x, bb.y, bb.z, bb.w};
#pragma unroll
        for (int pi = 0; pi < 4; pi++) {
            int p = r8*4 + pi;
            float inv = powf(10000.f, (-2.0f * (float)p) / 64.f);
            float sn, cs;
            sincosf((float)s * inv, &sn, &cs);
            float x1 = t[2*pi], x2 = t[2*pi+1];
            v[2*pi]   = (x1 * cs - x2 * sn) * scale;
            v[2*pi+1] = (x1 * sn + x2 * cs) * scale;
        }
    }
    __align__(16) __half hi[8], lo[8];
    split8(v, hi, lo);
    *(uint4*)&out[base + d]       = *(uint4*)hi;
    *(uint4*)&out[base + 192 + d] = *(uint4*)lo;
}

// ---------------- pack K (R10, verified) ----------------
__global__ void pack_k(const float* __restrict__ kv, const float* __restrict__ dall,
                       __half* __restrict__ out)
{
    long long idx = (long long)blockIdx.x * blockDim.x + threadIdx.x;
    if (idx >= (long long)BB*NH*SS*24) return;
    int c8 = (int)(idx % 24);
    int s  = (int)((idx / 24) % SS);
    int bh = (int)(idx / (24LL*SS));
    int b = bh / NH, h = bh % NH;
    size_t m = (size_t)b * SS + s;
    int d = c8 * 8;
    const float* src = (d < 128) ? &kv[m * (NH*256) + h*256 + d]
                                 : &dall[m * NDOWN + 2048 + (d - 128)];
    float4 a = ((const float4*)src)[0], bb = ((const float4*)src)[1];
    __align__(16) __half hh[8];
    hh[0]=__float2half(a.x);  hh[1]=__float2half(a.y);  hh[2]=__float2half(a.z);  hh[3]=__float2half(a.w);
    hh[4]=__float2half(bb.x); hh[5]=__float2half(bb.y); hh[6]=__float2half(bb.z); hh[7]=__float2half(bb.w);
    *(uint4*)&out[((size_t)bh * SS + s) * 192 + d] = *(uint4*)hh;
}

// ---------------- pack V transpose (R10, verified) ----------------
__global__ __launch_bounds__(256) void pack_v(const float* __restrict__ kv,
                                              __half* __restrict__ vt)
{
    __shared__ float vs[64][129];
    const int t = blockIdx.x, h = blockIdx.y, b = blockIdx.z;
    const int bh = b*NH + h;
    const int tid = threadIdx.x;
    for (int i = tid; i < 64*32; i += 256) {
        int r = i >> 5, d4 = (i & 31) * 4;
        size_t m = (size_t)b * SS + t*64 + r;
        float4 v = *(const float4*)&kv[m * (NH*256) + h*256 + 128 + d4];
        vs[r][d4] = v.x; vs[r][d4+1] = v.y; vs[r][d4+2] = v.z; vs[r][d4+3] = v.w;
    }
    __syncthreads();
    for (int i = tid; i < 128*8; i += 256) {
        int d = i >> 3, w8 = i & 7;
        int kk0 = w8 * 8;
        __align__(16) __half p[8];
#pragma unroll
        for (int k = 0; k < 8; k++) p[k] = __float2half(vs[kk0 + k][d]);
        *(uint4*)&vt[((size_t)bh * 128 + d) * SS + t*64 + kk0] = *(uint4*)p;
    }
}

// ============================================================
// HMMA flash attention — Q resident (R10 core, verified at 965us)
// ============================================================
#define KBASE 49152u
#define VBASE 73728u
#define PBASE 90112u
#define ATT_SMEM 108544

__global__ __launch_bounds__(256, 2) void attn_mma(
    const __half* __restrict__ Qsp, const __half* __restrict__ Ksp,
    const __half* __restrict__ Vt, __half* __restrict__ ats)
{
    extern __shared__ __align__(16) char smem[];
    const uint32_t sb = smem_u32(smem);
    const int qt = (int)gridDim.x - 1 - (int)blockIdx.x;
    const int h = blockIdx.y, b = blockIdx.z;
    const int bh = b*NH + h;
    const int q0 = qt * 64;
    const int tid = threadIdx.x, lane = tid & 31;
    const int wm = (tid >> 5) & 3, wn = tid >> 7;

    const __half* Qg = Qsp + ((size_t)bh * SS + q0) * 384;
    const __half* Kg = Ksp + (size_t)bh * SS * 192;
    const __half* Vg = Vt  + (size_t)bh * 128 * SS;

    float* redmax = (float*)(smem + 107520);
    float* redsum = (float*)(smem + 108032);

    {
        int r = tid >> 3, ch = tid & 7;
#pragma unroll
        for (int cq = 0; cq < 6; cq++) {
#pragma unroll
            for (int it = 0; it < 2; it++) {
                int rr = r + it*32;
                CPA16(sb + (uint32_t)cq*8192u + sw128(rr, ch),
                      Qg + (size_t)rr*384 + cq*64 + ch*8);
            }
        }
        CPCOMMIT();
    }

    float acc_o[8][4];
#pragma unroll
    for (int i = 0; i < 8; i++)
#pragma unroll
        for (int j = 0; j < 4; j++) acc_o[i][j] = 0.f;
    float m0 = -1e30f, m1 = -1e30f, l0 = 0.f, l1 = 0.f;

    const int a_row  = lane & 15;
    const int a_ch   = lane >> 4;
    const int b_nrow = (lane & 7) + ((lane & 16) ? 8 : 0);
    const int b_ch   = (lane >> 3) & 1;
    const int r0 = wm*16 + (lane >> 2);

    for (int t = 0; t <= qt; t++) {
        const int k0 = t * 64;
        {
            int r = tid >> 3, ch = tid & 7;
#pragma unroll
            for (int slot = 0; slot < 2; slot++) {
#pragma unroll
                for (int it = 0; it < 2; it++) {
                    int rr = r + it*32;
                    CPA16(sb + KBASE + (uint32_t)slot*8192u + sw128(rr, ch),
                          Kg + (size_t)(k0 + rr)*192 + slot*64 + ch*8);
                }
                CPCOMMIT();
            }
#pragma unroll
            for (int it = 0; it < 4; it++) {
                int i = tid + it*256;
                int d = i >> 3, vch = i & 7;
                CPA16(sb + VBASE + sw128(d, vch), Vg + (size_t)d*SS + t*64 + vch*8);
            }
            CPCOMMIT();
        }

        float acc_s[4][4];
#pragma unroll
        for (int i = 0; i < 4; i++)
#pragma unroll
            for (int j = 0; j < 4; j++) acc_s[i][j] = 0.f;

#pragma unroll
        for (int c = 0; c < 3; c++) {
            if (c < 2) { CPWAIT(2); } else { CPWAIT(0); }
            __syncthreads();
            if (c == 0) {
                int r = tid >> 3, ch = tid & 7;
#pragma unroll
                for (int it = 0; it < 2; it++) {
                    int rr = r + it*32;
                    CPA16(sb + KBASE + 2u*8192u + sw128(rr, ch),
                          Kg + (size_t)(k0 + rr)*192 + 2*64 + ch*8);
                }
                CPCOMMIT();
            }
            uint32_t kb = sb + KBASE + (uint32_t)c*8192u;
            uint32_t qh = sb + (uint32_t)c*8192u;
            uint32_t ql = sb + (uint32_t)(c+3)*8192u;
#pragma unroll
            for (int ks = 0; ks < 4; ks++) {
                uint32_t a0[4], a1[4];
                ldsm4(a0, qh + sw128(wm*16 + a_row, ks*2 + a_ch));
                ldsm4(a1, ql + sw128(wm*16 + a_row, ks*2 + a_ch));
#pragma unroll
                for (int g = 0; g < 2; g++) {
                    uint32_t bb[4];
                    ldsm4(bb, kb + sw128(wn*32 + g*16 + b_nrow, ks*2 + b_ch));
                    mma16816(acc_s[g*2],   a0, bb[0], bb[1]);
                    mma16816(acc_s[g*2+1], a0, bb[2], bb[3]);
                    mma16816(acc_s[g*2],   a1, bb[0], bb[1]);
                    mma16816(acc_s[g*2+1], a1, bb[2], bb[3]);
                }
            }
        }

        if (t == qt) {
#pragma unroll
            for (int nt = 0; nt < 4; nt++) {
                int colb = wn*32 + nt*8 + (lane & 3)*2;
                if (colb     > r0)     acc_s[nt][0] = -1e30f;
                if (colb + 1 > r0)     acc_s[nt][1] = -1e30f;
                if (colb     > r0 + 8) acc_s[nt][2] = -1e30f;
                if (colb + 1 > r0 + 8) acc_s[nt][3] = -1e30f;
            }
        }

        float mx0 = -1e30f, mx1 = -1e30f;
#pragma unroll
        for (int nt = 0; nt < 4; nt++) {
            mx0 = fmaxf(mx0, fmaxf(acc_s[nt][0], acc_s[nt][1]));
            mx1 = fmaxf(mx1, fmaxf(acc_s[nt][2], acc_s[nt][3]));
        }
        mx0 = fmaxf(mx0, __shfl_xor_sync(0xffffffffu, mx0, 1));
        mx0 = fmaxf(mx0, __shfl_xor_sync(0xffffffffu, mx0, 2));
        mx1 = fmaxf(mx1, __shfl_xor_sync(0xffffffffu, mx1, 1));
        mx1 = fmaxf(mx1, __shfl_xor_sync(0xffffffffu, mx1, 2));
        if ((lane & 3) == 0) {
            redmax[wn*64 + r0]     = mx0;
            redmax[wn*64 + r0 + 8] = mx1;
        }
        __syncthreads();
        float tm0 = fmaxf(mx0, redmax[(wn^1)*64 + r0]);
        float tm1 = fmaxf(mx1, redmax[(wn^1)*64 + r0 + 8]);
        float nm0 = fmaxf(m0, tm0), nm1 = fmaxf(m1, tm1);
        float f0 = __expf(m0 - nm0), f1 = __expf(m1 - nm1);

        float s0 = 0.f, s1 = 0.f;
#pragma unroll
        for (int nt = 0; nt < 4; nt++) {
            acc_s[nt][0] = __expf(acc_s[nt][0] - nm0);
            acc_s[nt][1] = __expf(acc_s[nt][1] - nm0);
            acc_s[nt][2] = __expf(acc_s[nt][2] - nm1);
            acc_s[nt][3] = __expf(acc_s[nt][3] - nm1);
            s0 += acc_s[nt][0] + acc_s[nt][1];
            s1 += acc_s[nt][2] + acc_s[nt][3];
        }
        s0 += __shfl_xor_sync(0xffffffffu, s0, 1);
        s0 += __shfl_xor_sync(0xffffffffu, s0, 2);
        s1 += __shfl_xor_sync(0xffffffffu, s1, 1);
        s1 += __shfl_xor_sync(0xffffffffu, s1, 2);
        if ((lane & 3) == 0) {
            redsum[wn*64 + r0]     = s0;
            redsum[wn*64 + r0 + 8] = s1;
        }
        {
            char* P = smem + PBASE;
            int colb = wn*32 + (lane & 3)*2;
#pragma unroll
            for (int nt = 0; nt < 4; nt++) {
                int col = colb + nt*8;
#pragma unroll
                for (int half = 0; half < 2; half++) {
                    float pa = acc_s[nt][half*2], pb = acc_s[nt][half*2+1];
                    int row = r0 + half*8;
                    __half ha = __float2half(pa), hb = __float2half(pb);
                    __half la = __float2half(pa - __half2float(ha));
                    __half lb = __float2half(pb - __half2float(hb));
                    uint32_t hi = (uint32_t)(*(uint16_t*)&ha) | ((uint32_t)(*(uint16_t*)&hb) << 16);
                    uint32_t lo = (uint32_t)(*(uint16_t*)&la) | ((uint32_t)(*(uint16_t*)&lb) << 16);
                    uint32_t* base = (uint32_t*)(P + row*272 + col*2);
                    base[0]  = hi;
                    base[32] = lo;
                }
            }
        }
        __syncthreads();
        float ts0 = s0 + redsum[(wn^1)*64 + r0];
        float ts1 = s1 + redsum[(wn^1)*64 + r0 + 8];
        l0 = l0 * f0 + ts0;
        l1 = l1 * f1 + ts1;
        m0 = nm0; m1 = nm1;
#pragma unroll
        for (int nt = 0; nt < 8; nt++) {
            acc_o[nt][0] *= f0; acc_o[nt][1] *= f0;
            acc_o[nt][2] *= f1; acc_o[nt][3] *= f1;
        }

#pragma unroll
        for (int pc = 0; pc < 2; pc++) {
            uint32_t pseg = (uint32_t)pc * 128u;
#pragma unroll
            for (int ks = 0; ks < 4; ks++) {
                uint32_t a[4];
                ldsm4(a, sb + PBASE + (uint32_t)((wm*16 + a_row)*272) + pseg
                         + (uint32_t)(ks*32 + a_ch*16));
#pragma unroll
                for (int g = 0; g < 4; g++) {
                    uint32_t bb[4];
                    ldsm4(bb, sb + VBASE + sw128(wn*64 + g*16 + b_nrow, ks*2 + b_ch));
                    mma16816(acc_o[g*2],   a, bb[0], bb[1]);
                    mma16816(acc_o[g*2+1], a, bb[2], bb[3]);
                }
            }
        }
        __syncthreads();
    }

    float il0 = 1.f / l0, il1 = 1.f / l1;
    size_t mrow0 = (size_t)b * SS + q0 + r0;
#pragma unroll
    for (int nt = 0; nt < 8; nt++) {
        int col = h*128 + wn*64 + nt*8 + (lane & 3)*2;
#pragma unroll
        for (int half = 0; half < 2; half++) {
            float oa = acc_o[nt][half*2]   * (half ? il1 : il0);
            float ob = acc_o[nt][half*2+1] * (half ? il1 : il0);
            size_t row = mrow0 + half*8;
            __half ha = __float2half(oa), hb = __float2half(ob);
            uint32_t hi = (uint32_t)(*(uint16_t*)&ha) | ((uint32_t)(*(uint16_t*)&hb) << 16);
            ((uint32_t*)(ats + row * 2048))[col >> 1] = hi;
        }
    }
}

// ---------------- host orchestration (R10 structure) ----------------
static void convA(const float* in, __half* out, int R, int Rpad, int C, int inPitch)
{
    long long tot = (long long)Rpad * (C >> 3);
    splitA_k<<<(int)((tot + 255) / 256), 256>>>(in, out, R, Rpad, C, inPitch);
}
static void convB(const float* in, __half* out, int R, int Rpad, int C, int inPitch)
{
    long long tot = (long long)Rpad * (C >> 3);
    cvtB_k<<<(int)((tot + 255) / 256), 256>>>(in, out, R, Rpad, C, inPitch);
}
static void gemmx(const __half* A, const __half* B, float* C, int M, int N, int K, int KA)
{
    cudaFuncSetAttribute(gemm_tc, cudaFuncAttributeMaxDynamicSharedMemorySize, GEMM_SMEM);
    dim3 grid((N + 127) / 128, M / 256);
    gemm_tc<<<grid, 256, GEMM_SMEM>>>(A, B, C, M, N, K, KA);
}

extern "C" void kernel_launch(void* const* d_in, const int* in_sizes, int n_in,
                              void* d_out, int out_size)
{
    const float* x        = (const float*)d_in[0];
    const float* wq_down  = (const float*)d_in[1];
    const float* q_norm_w = (const float*)d_in[2];
    const float* wq_up    = (const float*)d_in[3];
    const float* wq_rope  = (const float*)d_in[4];
    const float* wkv_down = (const float*)d_in[5];
    const float* kv_norm_w= (const float*)d_in[6];
    const float* wkv_up   = (const float*)d_in[7];
    const float* wk_rope  = (const float*)d_in[8];
    const float* wo       = (const float*)d_in[9];
    float* out = (float*)d_out;

    float *dall, *qnp, *kvu;
    cudaGetSymbolAddress((void**)&dall, g_dall);
    cudaGetSymbolAddress((void**)&qnp,  g_qnp);
    cudaGetSymbolAddress((void**)&kvu,  g_kvup);

    __half *xs, *wdall, *qcs, *wuall, *kvcs, *wkvu, *ats, *wos, *qsp, *ksp, *vt;
    cudaGetSymbolAddress((void**)&xs,    g_xs);
    cudaGetSymbolAddress((void**)&wdall, g_wdall);
    cudaGetSymbolAddress((void**)&qcs,   g_qcs);
    cudaGetSymbolAddress((void**)&wuall, g_wuall);
    cudaGetSymbolAddress((void**)&kvcs,  g_kvcs);
    cudaGetSymbolAddress((void**)&wkvu,  g_wkvu);
    cudaGetSymbolAddress((void**)&ats,   g_ats);
    cudaGetSymbolAddress((void**)&wos,   g_wos);
    cudaGetSymbolAddress((void**)&qsp,   g_qsp);
    cudaGetSymbolAddress((void**)&ksp,   g_ksp);
    cudaGetSymbolAddress((void**)&vt,    g_vt);

    // ---- stage 1: merged down projection ----
    convA(x,        xs,    MT,  MT,  DIMM, DIMM);
    convB(wq_down,  wdall,                         QR,  QR,  DIMM, DIMM);
    convB(wkv_down, wdall + (size_t)QR*DIMM,       KVR, KVR, DIMM, DIMM);
    convB(wk_rope,  wdall + (size_t)(QR+KVR)*DIMM, DR,  128, DIMM, DIMM);
    gemmx(xs, wdall, dall, MT, NDOWN, DIMM, 2*DIMM);

    // ---- fused rmsnorm -> split fp16; kr rope ----
    rmsnorm_split_k<<<MT, 256>>>(dall,      q_norm_w,  qcs,  QR,  NDOWN);
    rmsnorm_split_k<<<MT, 256>>>(dall + QR, kv_norm_w, kvcs, KVR, NDOWN);
    rope_k<<<(MT*32 + 255)/256, 256>>>(dall, NDOWN, QR+KVR, 1, DR, MT*32);

    // ---- stage 2: merged up projections ----
    convB(wq_up,   wuall,                      NH*DN, NH*DN, QR, QR);
    convB(wq_rope, wuall + (size_t)(NH*DN)*QR, NH*DR, NH*DR, QR, QR);
    gemmx(qcs,  wuall, qnp, MT, NUP, QR, 2*QR);
    convB(wkv_up, wkvu, NH*(DN+DVV), NH*(DN+DVV), KVR, KVR);
    gemmx(kvcs, wkvu,  kvu, MT, NH*(DN+DVV), KVR, 2*KVR);

    // ---- packs ----
    {
        long long tot = (long long)BB*NH*SS*24;
        rope_pack_q<<<(int)((tot + 255) / 256), 256>>>(qnp, qsp);
        pack_k<<<(int)((tot + 255) / 256), 256>>>(kvu, dall, ksp);
    }
    pack_v<<<dim3(SS/64, NH, BB), 256>>>(kvu, vt);

    // ---- HMMA flash attention (Q resident) ----
    cudaFuncSetAttribute(attn_mma, cudaFuncAttributeMaxDynamicSharedMemorySize, ATT_SMEM);
    attn_mma<<<dim3(SS/64, NH, BB), 256, ATT_SMEM>>>(qsp, ksp, vt, ats);

    // ---- output projection (1-term fp16) ----
    convB(wo, wos, DIMM, DIMM, NH*DVV, NH*DVV);
    gemmx(ats, wos, out, MT, DIMM, NH*DVV, NH*DVV);
}

// round 13
// speedup vs baseline: 1.3117x; 1.3117x over previous
#include <cuda_runtime.h>
#include <cuda_fp16.h>
#include <math.h>
#include <stdint.h>

#define BB 2
#define SS 2048
#define DIMM 2048
#define NH 16
#define QR 1536
#define KVR 512
#define DN 128
#define DR 64
#define DVV 128
#define MT (BB*SS)   // 4096 token rows

#define NDOWN 2112   // qc(1536) | kvc(512) | kr(64)
#define NDOWNP 2176
#define NUP 3072     // qn(2048) | qp(1024)

// ---------------- fp32 scratch ----------------
__device__ float g_dall[MT*NDOWN];
__device__ float g_qnp [MT*NUP];
__device__ float g_kvup[MT*NH*(DN+DVV)];

// ---------------- fp16 scratch (1-term: hi only everywhere dense) ----------
__device__ __half g_xs   [MT    * DIMM];
__device__ __half g_wdall[NDOWNP* DIMM];
__device__ __half g_qcs  [MT    * QR];
__device__ __half g_wuall[NUP   * QR];
__device__ __half g_kvcs [MT    * KVR];
__device__ __half g_wkvu [(NH*(DN+DVV)) * KVR];
__device__ __half g_ats  [MT    * (NH*DVV)];
__device__ __half g_wos  [DIMM  * (NH*DVV)];

// ---------------- attention packed operands (2-term Q kept) ---------------
__device__ __half g_qsp[BB*NH*SS*384];     // [bh][s][Qh(192)|Ql(192)]
__device__ __half g_ksp[BB*NH*SS*192];     // [bh][s][Kh(192)]
__device__ __half g_vt [BB*NH*128*SS];     // [bh][d][s]

// ============================================================
// helpers
// ============================================================
__device__ __forceinline__ uint32_t smem_u32(const void* p){
    uint32_t a;
    asm("{ .reg .u64 t; cvta.to.shared.u64 t, %1; cvt.u32.u64 %0, t; }" : "=r"(a) : "l"(p));
    return a;
}
#define CPA16(dst, src) asm volatile("cp.async.cg.shared.global [%0], [%1], 16;" :: "r"(dst), "l"(src))
#define CPCOMMIT()      asm volatile("cp.async.commit_group;")
#define CPWAIT(n)       asm volatile("cp.async.wait_group %0;" :: "n"(n))

__device__ __forceinline__ void ldsm4(uint32_t* r, uint32_t addr){
    asm volatile("ldmatrix.sync.aligned.m8n8.x4.shared.b16 {%0,%1,%2,%3}, [%4];"
        : "=r"(r[0]), "=r"(r[1]), "=r"(r[2]), "=r"(r[3]) : "r"(addr));
}
__device__ __forceinline__ void mma16816(float* c, const uint32_t* a, uint32_t b0, uint32_t b1){
    asm volatile("mma.sync.aligned.m16n8k16.row.col.f32.f16.f16.f32 "
        "{%0,%1,%2,%3}, {%4,%5,%6,%7}, {%8,%9}, {%0,%1,%2,%3};"
        : "+f"(c[0]), "+f"(c[1]), "+f"(c[2]), "+f"(c[3])
        : "r"(a[0]), "r"(a[1]), "r"(a[2]), "r"(a[3]), "r"(b0), "r"(b1));
}
__device__ __forceinline__ uint32_t sw128(int row, int chunk){
    return (uint32_t)(row * 128 + ((chunk ^ (row & 7)) * 16));
}
__device__ __forceinline__ void split8(const float* v, __half* hi, __half* lo){
#pragma unroll
    for (int k = 0; k < 8; k++) {
        __half h = __float2half(v[k]);
        hi[k] = h;
        lo[k] = __float2half(v[k] - __half2float(h));
    }
}

// ============================================================
// vectorized fp32 -> fp16 (hi only), 8 elems/thread
// ============================================================
__global__ void cvtB_k(const float* __restrict__ in, __half* __restrict__ out,
                       int R, int Rpad, int C, int inPitch)
{
    long long i = (long long)blockIdx.x * blockDim.x + threadIdx.x;
    int C8 = C >> 3;
    long long tot = (long long)Rpad * C8;
    if (i >= tot) return;
    int r = (int)(i / C8), c = ((int)(i % C8)) << 3;
    __align__(16) __half h[8];
    if (r < R) {
        float4 a = *(const float4*)&in[(size_t)r * inPitch + c];
        float4 b = *(const float4*)&in[(size_t)r * inPitch + c + 4];
        h[0]=__float2half(a.x); h[1]=__float2half(a.y); h[2]=__float2half(a.z); h[3]=__float2half(a.w);
        h[4]=__float2half(b.x); h[5]=__float2half(b.y); h[6]=__float2half(b.z); h[7]=__float2half(b.w);
    } else {
#pragma unroll
        for (int k = 0; k < 8; k++) h[k] = __float2half(0.f);
    }
    *(uint4*)&out[(size_t)r * C + c] = *(uint4*)h;
}

// ============================================================
// fp16 GEMM — exact R10 core (128x128, 3 stages, 2 CTAs/SM; verified 965us)
// Now always KA == K (1-term), interface kept.
// ============================================================
#define STAGES 3
#define STAGE_BYTES 32768
#define GEMM_SMEM (STAGES*STAGE_BYTES)

__global__ __launch_bounds__(256, 2) void gemm_tc(
    const __half* __restrict__ A, const __half* __restrict__ B,
    float* __restrict__ C, int M, int N, int K, int KA)
{
    extern __shared__ __align__(16) char smem[];
    const uint32_t sb = smem_u32(smem);
    const int m0 = blockIdx.y * 128, n0 = blockIdx.x * 128;
    const int tid = threadIdx.x, lane = tid & 31;
    const int wm = (tid >> 5) & 3;
    const int wn = tid >> 7;

    float acc[2][8][4];
#pragma unroll
    for (int i = 0; i < 2; i++)
#pragma unroll
        for (int j = 0; j < 8; j++)
#pragma unroll
            for (int q = 0; q < 4; q++) acc[i][j][q] = 0.f;

    const int KT  = KA >> 6;
    const int KTh = K >> 6;
    const __half* Ag0 = A + (size_t)m0 * KA;
    const __half* Bg0 = B + (size_t)n0 * K;

    const int fr = tid >> 3;
    const int fc = tid & 7;

    auto fill = [&](int j){
        uint32_t base = sb + (uint32_t)(j % STAGES) * STAGE_BYTES;
        int ka = j << 6;
        int kb = (j >= KTh ? j - KTh : j) << 6;
#pragma unroll
        for (int i = 0; i < 4; i++) {
            int r = fr + i * 32;
            CPA16(base + sw128(r, fc), Ag0 + (size_t)r * KA + ka + fc*8);
        }
#pragma unroll
        for (int i = 0; i < 4; i++) {
            int r = fr + i * 32;
            CPA16(base + 16384u + sw128(r, fc), Bg0 + (size_t)r * K + kb + fc*8);
        }
        CPCOMMIT();
    };

    fill(0);
    fill(1);

    const int a_row  = lane & 15;
    const int a_ch   = lane >> 4;
    const int b_nrow = (lane & 7) + ((lane & 16) ? 8 : 0);
    const int b_ch   = (lane >> 3) & 1;

    for (int kt = 0; kt < KT; kt++) {
        CPWAIT(1);
        __syncthreads();
        if (kt + 2 < KT) fill(kt + 2);
        else CPCOMMIT();

        uint32_t aT = sb + (uint32_t)(kt % STAGES) * STAGE_BYTES;
        uint32_t bT = aT + 16384u;
#pragma unroll
        for (int ks = 0; ks < 4; ks++) {
            uint32_t a[2][4];
#pragma unroll
            for (int i = 0; i < 2; i++)
                ldsm4(a[i], aT + sw128(wm*32 + i*16 + a_row, ks*2 + a_ch));
            uint32_t b[4][4];
#pragma unroll
            for (int g = 0; g < 4; g++)
                ldsm4(b[g], bT + sw128(wn*64 + g*16 + b_nrow, ks*2 + b_ch));
#pragma unroll
            for (int i = 0; i < 2; i++)
#pragma unroll
                for (int g = 0; g < 4; g++) {
                    mma16816(acc[i][2*g],   a[i], b[g][0], b[g][1]);
                    mma16816(acc[i][2*g+1], a[i], b[g][2], b[g][3]);
                }
        }
    }

    const int rb = m0 + wm*32;
    const int cb = n0 + wn*64;
#pragma unroll
    for (int i = 0; i < 2; i++)
#pragma unroll
        for (int j = 0; j < 8; j++) {
            int c = cb + j*8 + (lane & 3)*2;
            if (c < N) {
                int r = rb + i*16 + (lane >> 2);
                *(float2*)&C[(size_t)r * N + c]     = make_float2(acc[i][j][0], acc[i][j][1]);
                *(float2*)&C[(size_t)(r+8) * N + c] = make_float2(acc[i][j][2], acc[i][j][3]);
            }
        }
}

// ---------------- RMSNorm -> fp16 hi-only (vectorized) ----------------
__global__ void rmsnorm_h_k(const float* __restrict__ x, const float* __restrict__ w,
                            __half* __restrict__ out, int W, int pitch)
{
    const int row = blockIdx.x;
    const float* xr = x + (size_t)row * pitch;
    const float4* x4 = (const float4*)xr;
    float ss = 0.f;
    int W4 = W >> 2;
    for (int i = threadIdx.x; i < W4; i += blockDim.x) {
        float4 v = x4[i];
        ss += v.x*v.x + v.y*v.y + v.z*v.z + v.w*v.w;
    }
    __shared__ float red[32];
#pragma unroll
    for (int o = 16; o; o >>= 1) ss += __shfl_down_sync(0xffffffffu, ss, o);
    if ((threadIdx.x & 31) == 0) red[threadIdx.x >> 5] = ss;
    __syncthreads();
    if (threadIdx.x < 32) {
        float v = (threadIdx.x < (blockDim.x >> 5)) ? red[threadIdx.x] : 0.f;
#pragma unroll
        for (int o = 16; o; o >>= 1) v += __shfl_down_sync(0xffffffffu, v, o);
        if (threadIdx.x == 0) red[0] = rsqrtf(v / (float)W + 1e-6f);
    }
    __syncthreads();
    float r = red[0];
    __half* orow = out + (size_t)row * W;
    const float4* w4 = (const float4*)w;
    int W8 = W >> 3;
    for (int i8 = threadIdx.x; i8 < W8; i8 += blockDim.x) {
        float4 a = x4[i8*2], b = x4[i8*2+1];
        float4 wa = w4[i8*2], wb = w4[i8*2+1];
        __align__(16) __half h[8];
        h[0]=__float2half(a.x*r*wa.x); h[1]=__float2half(a.y*r*wa.y);
        h[2]=__float2half(a.z*r*wa.z); h[3]=__float2half(a.w*r*wa.w);
        h[4]=__float2half(b.x*r*wb.x); h[5]=__float2half(b.y*r*wb.y);
        h[6]=__float2half(b.z*r*wb.z); h[7]=__float2half(b.w*r*wb.w);
        *(uint4*)&orow[i8*8] = *(uint4*)h;
    }
}

// ---------------- RoPE on k_rope slice of dall ----------------
__global__ void rope_k(float* __restrict__ x, int pitch, int colOff,
                       int nheads, int d, int total_pairs)
{
    int idx = blockIdx.x * blockDim.x + threadIdx.x;
    if (idx >= total_pairs) return;
    int pairs_per_row = nheads * (d / 2);
    int row = idx / pairs_per_row;
    int p   = idx % pairs_per_row;
    int h = p / (d / 2);
    int i = p % (d / 2);
    int pos = row % SS;
    float inv = powf(10000.f, (-2.0f * (float)i) / (float)d);
    float ang = (float)pos * inv;
    float s, c;
    sincosf(ang, &s, &c);
    float* base = x + (size_t)row * pitch + colOff + h * d + 2 * i;
    float x1 = base[0], x2 = base[1];
    base[0] = x1 * c - x2 * s;
    base[1] = x1 * s + x2 * c;
}

// ---------------- fused Q rope + split pack (2-term kept) ----------------
__global__ void rope_pack_q(const float* __restrict__ qnp, __half* __restrict__ out)
{
    long long idx = (long long)blockIdx.x * blockDim.x + threadIdx.x;
    if (idx >= (long long)BB*NH*SS*24) return;
    int c8 = (int)(idx % 24);
    int s  = (int)((idx / 24) % SS);
    int bh = (int)(idx / (24LL*SS));
    int b = bh / NH, h = bh % NH;
    size_t m = (size_t)b * SS + s;
    const float scale = 0.072168783648703220563f;
    size_t base = ((size_t)bh * SS + s) * 384;
    int d = c8 * 8;
    float v[8];
    if (c8 < 16) {
        const float4* src = (const float4*)&qnp[m * NUP + h*128 + d];
        float4 a = src[0], bb = src[1];
        v[0]=a.x; v[1]=a.y; v[2]=a.z; v[3]=a.w; v[4]=bb.x; v[5]=bb.y; v[6]=bb.z; v[7]=bb.w;
#pragma unroll
        for (int k = 0; k < 8; k++) v[k] *= scale;
    } else {
        int r8 = c8 - 16;
        const float4* src = (const float4*)&qnp[m * NUP + 2048 + h*64 + r8*8];
        float4 a = src[0], bb = src[1];
        float t[8] = {a.x, a.y, a.z, a.w, bb.x, bb.y, bb.z, bb.w};
#pragma unroll
        for (int pi = 0; pi < 4; pi++) {
            int p = r8*4 + pi;
            float inv = powf(10000.f, (-2.0f * (float)p) / 64.f);
            float sn, cs;
            sincosf((float)s * inv, &sn, &cs);
            float x1 = t[2*pi], x2 = t[2*pi+1];
            v[2*pi]   = (x1 * cs - x2 * sn) * scale;
            v[2*pi+1] = (x1 * sn + x2 * cs) * scale;
        }
    }
    __align__(16) __half hi[8], lo[8];
    split8(v, hi, lo);
    *(uint4*)&out[base + d]       = *(uint4*)hi;
    *(uint4*)&out[base + 192 + d] = *(uint4*)lo;
}

// ---------------- pack K ----------------
__global__ void pack_k(const float* __restrict__ kv, const float* __restrict__ dall,
                       __half* __restrict__ out)
{
    long long idx = (long long)blockIdx.x * blockDim.x + threadIdx.x;
    if (idx >= (long long)BB*NH*SS*24) return;
    int c8 = (int)(idx % 24);
    int s  = (int)((idx / 24) % SS);
    int bh = (int)(idx / (24LL*SS));
    int b = bh / NH, h = bh % NH;
    size_t m = (size_t)b * SS + s;
    int d = c8 * 8;
    const float* src = (d < 128) ? &kv[m * (NH*256) + h*256 + d]
                                 : &dall[m * NDOWN + 2048 + (d - 128)];
    float4 a = ((const float4*)src)[0], bb = ((const float4*)src)[1];
    __align__(16) __half hh[8];
    hh[0]=__float2half(a.x);  hh[1]=__float2half(a.y);  hh[2]=__float2half(a.z);  hh[3]=__float2half(a.w);
    hh[4]=__float2half(bb.x); hh[5]=__float2half(bb.y); hh[6]=__float2half(bb.z); hh[7]=__float2half(bb.w);
    *(uint4*)&out[((size_t)bh * SS + s) * 192 + d] = *(uint4*)hh;
}

// ---------------- pack V transpose ----------------
__global__ __launch_bounds__(256) void pack_v(const float* __restrict__ kv,
                                              __half* __restrict__ vt)
{
    __shared__ float vs[64][129];
    const int t = blockIdx.x, h = blockIdx.y, b = blockIdx.z;
    const int bh = b*NH + h;
    const int tid = threadIdx.x;
    for (int i = tid; i < 64*32; i += 256) {
        int r = i >> 5, d4 = (i & 31) * 4;
        size_t m = (size_t)b * SS + t*64 + r;
        float4 v = *(const float4*)&kv[m * (NH*256) + h*256 + 128 + d4];
        vs[r][d4] = v.x; vs[r][d4+1] = v.y; vs[r][d4+2] = v.z; vs[r][d4+3] = v.w;
    }
    __syncthreads();
    for (int i = tid; i < 128*8; i += 256) {
        int d = i >> 3, w8 = i & 7;
        int kk0 = w8 * 8;
        __align__(16) __half p[8];
#pragma unroll
        for (int k = 0; k < 8; k++) p[k] = __float2half(vs[kk0 + k][d]);
        *(uint4*)&vt[((size_t)bh * 128 + d) * SS + t*64 + kk0] = *(uint4*)p;
    }
}

// ============================================================
// HMMA flash attention — Q resident (exact R10 core, verified)
// ============================================================
#define KBASE 49152u
#define VBASE 73728u
#define PBASE 90112u
#define ATT_SMEM 108544

__global__ __launch_bounds__(256, 2) void attn_mma(
    const __half* __restrict__ Qsp, const __half* __restrict__ Ksp,
    const __half* __restrict__ Vt, __half* __restrict__ ats)
{
    extern __shared__ __align__(16) char smem[];
    const uint32_t sb = smem_u32(smem);
    const int qt = (int)gridDim.x - 1 - (int)blockIdx.x;
    const int h = blockIdx.y, b = blockIdx.z;
    const int bh = b*NH + h;
    const int q0 = qt * 64;
    const int tid = threadIdx.x, lane = tid & 31;
    const int wm = (tid >> 5) & 3, wn = tid >> 7;

    const __half* Qg = Qsp + ((size_t)bh * SS + q0) * 384;
    const __half* Kg = Ksp + (size_t)bh * SS * 192;
    const __half* Vg = Vt  + (size_t)bh * 128 * SS;

    float* redmax = (float*)(smem + 107520);
    float* redsum = (float*)(smem + 108032);

    {
        int r = tid >> 3, ch = tid & 7;
#pragma unroll
        for (int cq = 0; cq < 6; cq++) {
#pragma unroll
            for (int it = 0; it < 2; it++) {
                int rr = r + it*32;
                CPA16(sb + (uint32_t)cq*8192u + sw128(rr, ch),
                      Qg + (size_t)rr*384 + cq*64 + ch*8);
            }
        }
        CPCOMMIT();
    }

    float acc_o[8][4];
#pragma unroll
    for (int i = 0; i < 8; i++)
#pragma unroll
        for (int j = 0; j < 4; j++) acc_o[i][j] = 0.f;
    float m0 = -1e30f, m1 = -1e30f, l0 = 0.f, l1 = 0.f;

    const int a_row  = lane & 15;
    const int a_ch   = lane >> 4;
    const int b_nrow = (lane & 7) + ((lane & 16) ? 8 : 0);
    const int b_ch   = (lane >> 3) & 1;
    const int r0 = wm*16 + (lane >> 2);

    for (int t = 0; t <= qt; t++) {
        const int k0 = t * 64;
        {
            int r = tid >> 3, ch = tid & 7;
#pragma unroll
            for (int slot = 0; slot < 2; slot++) {
#pragma unroll
                for (int it = 0; it < 2; it++) {
                    int rr = r + it*32;
                    CPA16(sb + KBASE + (uint32_t)slot*8192u + sw128(rr, ch),
                          Kg + (size_t)(k0 + rr)*192 + slot*64 + ch*8);
                }
                CPCOMMIT();
            }
#pragma unroll
            for (int it = 0; it < 4; it++) {
                int i = tid + it*256;
                int d = i >> 3, vch = i & 7;
                CPA16(sb + VBASE + sw128(d, vch), Vg + (size_t)d*SS + t*64 + vch*8);
            }
            CPCOMMIT();
        }

        float acc_s[4][4];
#pragma unroll
        for (int i = 0; i < 4; i++)
#pragma unroll
            for (int j = 0; j < 4; j++) acc_s[i][j] = 0.f;

#pragma unroll
        for (int c = 0; c < 3; c++) {
            if (c < 2) { CPWAIT(2); } else { CPWAIT(0); }
            __syncthreads();
            if (c == 0) {
                int r = tid >> 3, ch = tid & 7;
#pragma unroll
                for (int it = 0; it < 2; it++) {
                    int rr = r + it*32;
                    CPA16(sb + KBASE + 2u*8192u + sw128(rr, ch),
                          Kg + (size_t)(k0 + rr)*192 + 2*64 + ch*8);
                }
                CPCOMMIT();
            }
            uint32_t kb = sb + KBASE + (uint32_t)c*8192u;
            uint32_t qh = sb + (uint32_t)c*8192u;
            uint32_t ql = sb + (uint32_t)(c+3)*8192u;
#pragma unroll
            for (int ks = 0; ks < 4; ks++) {
                uint32_t a0[4], a1[4];
                ldsm4(a0, qh + sw128(wm*16 + a_row, ks*2 + a_ch));
                ldsm4(a1, ql + sw128(wm*16 + a_row, ks*2 + a_ch));
#pragma unroll
                for (int g = 0; g < 2; g++) {
                    uint32_t bb[4];
                    ldsm4(bb, kb + sw128(wn*32 + g*16 + b_nrow, ks*2 + b_ch));
                    mma16816(acc_s[g*2],   a0, bb[0], bb[1]);
                    mma16816(acc_s[g*2+1], a0, bb[2], bb[3]);
                    mma16816(acc_s[g*2],   a1, bb[0], bb[1]);
                    mma16816(acc_s[g*2+1], a1, bb[2], bb[3]);
                }
            }
        }

        if (t == qt) {
#pragma unroll
            for (int nt = 0; nt < 4; nt++) {
                int colb = wn*32 + nt*8 + (lane & 3)*2;
                if (colb     > r0)     acc_s[nt][0] = -1e30f;
                if (colb + 1 > r0)     acc_s[nt][1] = -1e30f;
                if (colb     > r0 + 8) acc_s[nt][2] = -1e30f;
                if (colb + 1 > r0 + 8) acc_s[nt][3] = -1e30f;
            }
        }

        float mx0 = -1e30f, mx1 = -1e30f;
#pragma unroll
        for (int nt = 0; nt < 4; nt++) {
            mx0 = fmaxf(mx0, fmaxf(acc_s[nt][0], acc_s[nt][1]));
            mx1 = fmaxf(mx1, fmaxf(acc_s[nt][2], acc_s[nt][3]));
        }
        mx0 = fmaxf(mx0, __shfl_xor_sync(0xffffffffu, mx0, 1));
        mx0 = fmaxf(mx0, __shfl_xor_sync(0xffffffffu, mx0, 2));
        mx1 = fmaxf(mx1, __shfl_xor_sync(0xffffffffu, mx1, 1));
        mx1 = fmaxf(mx1, __shfl_xor_sync(0xffffffffu, mx1, 2));
        if ((lane & 3) == 0) {
            redmax[wn*64 + r0]     = mx0;
            redmax[wn*64 + r0 + 8] = mx1;
        }
        __syncthreads();
        float tm0 = fmaxf(mx0, redmax[(wn^1)*64 + r0]);
        float tm1 = fmaxf(mx1, redmax[(wn^1)*64 + r0 + 8]);
        float nm0 = fmaxf(m0, tm0), nm1 = fmaxf(m1, tm1);
        float f0 = __expf(m0 - nm0), f1 = __expf(m1 - nm1);

        float s0 = 0.f, s1 = 0.f;
#pragma unroll
        for (int nt = 0; nt < 4; nt++) {
            acc_s[nt][0] = __expf(acc_s[nt][0] - nm0);
            acc_s[nt][1] = __expf(acc_s[nt][1] - nm0);
            acc_s[nt][2] = __expf(acc_s[nt][2] - nm1);
            acc_s[nt][3] = __expf(acc_s[nt][3] - nm1);
            s0 += acc_s[nt][0] + acc_s[nt][1];
            s1 += acc_s[nt][2] + acc_s[nt][3];
        }
        s0 += __shfl_xor_sync(0xffffffffu, s0, 1);
        s0 += __shfl_xor_sync(0xffffffffu, s0, 2);
        s1 += __shfl_xor_sync(0xffffffffu, s1, 1);
        s1 += __shfl_xor_sync(0xffffffffu, s1, 2);
        if ((lane & 3) == 0) {
            redsum[wn*64 + r0]     = s0;
            redsum[wn*64 + r0 + 8] = s1;
        }
        {
            char* P = smem + PBASE;
            int colb = wn*32 + (lane & 3)*2;
#pragma unroll
            for (int nt = 0; nt < 4; nt++) {
                int col = colb + nt*8;
#pragma unroll
                for (int half = 0; half < 2; half++) {
                    float pa = acc_s[nt][half*2], pb = acc_s[nt][half*2+1];
                    int row = r0 + half*8;
                    __half ha = __float2half(pa), hb = __float2half(pb);
                    __half la = __float2half(pa - __half2float(ha));
                    __half lb = __float2half(pb - __half2float(hb));
                    uint32_t hi = (uint32_t)(*(uint16_t*)&ha) | ((uint32_t)(*(uint16_t*)&hb) << 16);
                    uint32_t lo = (uint32_t)(*(uint16_t*)&la) | ((uint32_t)(*(uint16_t*)&lb) << 16);
                    uint32_t* base = (uint32_t*)(P + row*272 + col*2);
                    base[0]  = hi;
                    base[32] = lo;
                }
            }
        }
        __syncthreads();
        float ts0 = s0 + redsum[(wn^1)*64 + r0];
        float ts1 = s1 + redsum[(wn^1)*64 + r0 + 8];
        l0 = l0 * f0 + ts0;
        l1 = l1 * f1 + ts1;
        m0 = nm0; m1 = nm1;
#pragma unroll
        for (int nt = 0; nt < 8; nt++) {
            acc_o[nt][0] *= f0; acc_o[nt][1] *= f0;
            acc_o[nt][2] *= f1; acc_o[nt][3] *= f1;
        }

#pragma unroll
        for (int pc = 0; pc < 2; pc++) {
            uint32_t pseg = (uint32_t)pc * 128u;
#pragma unroll
            for (int ks = 0; ks < 4; ks++) {
                uint32_t a[4];
                ldsm4(a, sb + PBASE + (uint32_t)((wm*16 + a_row)*272) + pseg
                         + (uint32_t)(ks*32 + a_ch*16));
#pragma unroll
                for (int g = 0; g < 4; g++) {
                    uint32_t bb[4];
                    ldsm4(bb, sb + VBASE + sw128(wn*64 + g*16 + b_nrow, ks*2 + b_ch));
                    mma16816(acc_o[g*2],   a, bb[0], bb[1]);
                    mma16816(acc_o[g*2+1], a, bb[2], bb[3]);
                }
            }
        }
        __syncthreads();
    }

    float il0 = 1.f / l0, il1 = 1.f / l1;
    size_t mrow0 = (size_t)b * SS + q0 + r0;
#pragma unroll
    for (int nt = 0; nt < 8; nt++) {
        int col = h*128 + wn*64 + nt*8 + (lane & 3)*2;
#pragma unroll
        for (int half = 0; half < 2; half++) {
            float oa = acc_o[nt][half*2]   * (half ? il1 : il0);
            float ob = acc_o[nt][half*2+1] * (half ? il1 : il0);
            size_t row = mrow0 + half*8;
            __half ha = __float2half(oa), hb = __float2half(ob);
            uint32_t hi = (uint32_t)(*(uint16_t*)&ha) | ((uint32_t)(*(uint16_t*)&hb) << 16);
            ((uint32_t*)(ats + row * 2048))[col >> 1] = hi;
        }
    }
}

// ---------------- host orchestration ----------------
static void convB(const float* in, __half* out, int R, int Rpad, int C, int inPitch)
{
    long long tot = (long long)Rpad * (C >> 3);
    cvtB_k<<<(int)((tot + 255) / 256), 256>>>(in, out, R, Rpad, C, inPitch);
}
static void gemmx(const __half* A, const __half* B, float* C, int M, int N, int K)
{
    cudaFuncSetAttribute(gemm_tc, cudaFuncAttributeMaxDynamicSharedMemorySize, GEMM_SMEM);
    dim3 grid((N + 127) / 128, M / 128);
    gemm_tc<<<grid, 256, GEMM_SMEM>>>(A, B, C, M, N, K, K);
}

extern "C" void kernel_launch(void* const* d_in, const int* in_sizes, int n_in,
                              void* d_out, int out_size)
{
    const float* x        = (const float*)d_in[0];
    const float* wq_down  = (const float*)d_in[1];
    const float* q_norm_w = (const float*)d_in[2];
    const float* wq_up    = (const float*)d_in[3];
    const float* wq_rope  = (const float*)d_in[4];
    const float* wkv_down = (const float*)d_in[5];
    const float* kv_norm_w= (const float*)d_in[6];
    const float* wkv_up   = (const float*)d_in[7];
    const float* wk_rope  = (const float*)d_in[8];
    const float* wo       = (const float*)d_in[9];
    float* out = (float*)d_out;

    float *dall, *qnp, *kvu;
    cudaGetSymbolAddress((void**)&dall, g_dall);
    cudaGetSymbolAddress((void**)&qnp,  g_qnp);
    cudaGetSymbolAddress((void**)&kvu,  g_kvup);

    __half *xs, *wdall, *qcs, *wuall, *kvcs, *wkvu, *ats, *wos, *qsp, *ksp, *vt;
    cudaGetSymbolAddress((void**)&xs,    g_xs);
    cudaGetSymbolAddress((void**)&wdall, g_wdall);
    cudaGetSymbolAddress((void**)&qcs,   g_qcs);
    cudaGetSymbolAddress((void**)&wuall, g_wuall);
    cudaGetSymbolAddress((void**)&kvcs,  g_kvcs);
    cudaGetSymbolAddress((void**)&wkvu,  g_wkvu);
    cudaGetSymbolAddress((void**)&ats,   g_ats);
    cudaGetSymbolAddress((void**)&wos,   g_wos);
    cudaGetSymbolAddress((void**)&qsp,   g_qsp);
    cudaGetSymbolAddress((void**)&ksp,   g_ksp);
    cudaGetSymbolAddress((void**)&vt,    g_vt);

    // ---- stage 1: merged down projection (all 1-term) ----
    convB(x,        xs,    MT,  MT,  DIMM, DIMM);
    convB(wq_down,  wdall,                         QR,  QR,  DIMM, DIMM);
    convB(wkv_down, wdall + (size_t)QR*DIMM,       KVR, KVR, DIMM, DIMM);
    convB(wk_rope,  wdall + (size_t)(QR+KVR)*DIMM, DR,  128, DIMM, DIMM);
    gemmx(xs, wdall, dall, MT, NDOWN, DIMM);

    // ---- rmsnorm -> fp16 hi; kr rope ----
    rmsnorm_h_k<<<MT, 256>>>(dall,      q_norm_w,  qcs,  QR,  NDOWN);
    rmsnorm_h_k<<<MT, 256>>>(dall + QR, kv_norm_w, kvcs, KVR, NDOWN);
    rope_k<<<(MT*32 + 255)/256, 256>>>(dall, NDOWN, QR+KVR, 1, DR, MT*32);

    // ---- stage 2: merged up projections (1-term) ----
    convB(wq_up,   wuall,                      NH*DN, NH*DN, QR, QR);
    convB(wq_rope, wuall + (size_t)(NH*DN)*QR, NH*DR, NH*DR, QR, QR);
    gemmx(qcs,  wuall, qnp, MT, NUP, QR);
    convB(wkv_up, wkvu, NH*(DN+DVV), NH*(DN+DVV), KVR, KVR);
    gemmx(kvcs, wkvu,  kvu, MT, NH*(DN+DVV), KVR);

    // ---- packs ----
    {
        long long tot = (long long)BB*NH*SS*24;
        rope_pack_q<<<(int)((tot + 255) / 256), 256>>>(qnp, qsp);
        pack_k<<<(int)((tot + 255) / 256), 256>>>(kvu, dall, ksp);
    }
    pack_v<<<dim3(SS/64, NH, BB), 256>>>(kvu, vt);

    // ---- HMMA flash attention (Q resident, 2-term S) ----
    cudaFuncSetAttribute(attn_mma, cudaFuncAttributeMaxDynamicSharedMemorySize, ATT_SMEM);
    attn_mma<<<dim3(SS/64, NH, BB), 256, ATT_SMEM>>>(qsp, ksp, vt, ats);

    // ---- output projection (1-term) ----
    convB(wo, wos, DIMM, DIMM, NH*DVV, NH*DVV);
    gemmx(ats, wos, out, MT, DIMM, NH*DVV);
}

// round 14
// speedup vs baseline: 1.3637x; 1.0397x over previous
#include <cuda_runtime.h>
#include <cuda_fp16.h>
#include <math.h>
#include <stdint.h>

#define BB 2
#define SS 2048
#define DIMM 2048
#define NH 16
#define QR 1536
#define KVR 512
#define DN 128
#define DR 64
#define DVV 128
#define MT (BB*SS)

#define NDOWN 2112
#define NDOWNP 2176
#define NUP 3072

// ---------------- fp32 scratch ----------------
__device__ float g_dall[MT*NDOWN];

// ---------------- fp16 scratch ----------------
__device__ __half g_xs   [MT    * DIMM];
__device__ __half g_wdall[NDOWNP* DIMM];
__device__ __half g_qcs  [MT    * QR];
__device__ __half g_wuall[NUP   * QR];
__device__ __half g_kvcs [MT    * KVR];
__device__ __half g_wkvu [(NH*(DN+DVV)) * KVR];
__device__ __half g_kvu16[MT    * (NH*(DN+DVV))];   // fp16 kv_up (from GEMM)
__device__ __half g_ats  [MT    * (NH*DVV)];
__device__ __half g_wos  [DIMM  * (NH*DVV)];

// ---------------- attention packed operands ----------------
__device__ __half g_qsp[BB*NH*SS*384];     // [bh][s][Qh|Ql]  (written by fused GEMM)
__device__ __half g_ksp[BB*NH*SS*192];
__device__ __half g_vt [BB*NH*128*SS];

// ============================================================
// helpers
// ============================================================
__device__ __forceinline__ uint32_t smem_u32(const void* p){
    uint32_t a;
    asm("{ .reg .u64 t; cvta.to.shared.u64 t, %1; cvt.u32.u64 %0, t; }" : "=r"(a) : "l"(p));
    return a;
}
#define CPA16(dst, src) asm volatile("cp.async.cg.shared.global [%0], [%1], 16;" :: "r"(dst), "l"(src))
#define CPCOMMIT()      asm volatile("cp.async.commit_group;")
#define CPWAIT(n)       asm volatile("cp.async.wait_group %0;" :: "n"(n))

__device__ __forceinline__ void ldsm4(uint32_t* r, uint32_t addr){
    asm volatile("ldmatrix.sync.aligned.m8n8.x4.shared.b16 {%0,%1,%2,%3}, [%4];"
        : "=r"(r[0]), "=r"(r[1]), "=r"(r[2]), "=r"(r[3]) : "r"(addr));
}
__device__ __forceinline__ void mma16816(float* c, const uint32_t* a, uint32_t b0, uint32_t b1){
    asm volatile("mma.sync.aligned.m16n8k16.row.col.f32.f16.f16.f32 "
        "{%0,%1,%2,%3}, {%4,%5,%6,%7}, {%8,%9}, {%0,%1,%2,%3};"
        : "+f"(c[0]), "+f"(c[1]), "+f"(c[2]), "+f"(c[3])
        : "r"(a[0]), "r"(a[1]), "r"(a[2]), "r"(a[3]), "r"(b0), "r"(b1));
}
__device__ __forceinline__ uint32_t sw128(int row, int chunk){
    return (uint32_t)(row * 128 + ((chunk ^ (row & 7)) * 16));
}
__device__ __forceinline__ uint32_t pack2h(float a, float b){
    __half ha = __float2half(a), hb = __float2half(b);
    return (uint32_t)(*(uint16_t*)&ha) | ((uint32_t)(*(uint16_t*)&hb) << 16);
}
__device__ __forceinline__ void split8(const float* v, __half* hi, __half* lo){
#pragma unroll
    for (int k = 0; k < 8; k++) {
        __half h = __float2half(v[k]);
        hi[k] = h;
        lo[k] = __float2half(v[k] - __half2float(h));
    }
}

// ============================================================
// conversions
// ============================================================
__global__ void cvtB_k(const float* __restrict__ in, __half* __restrict__ out,
                       int R, int Rpad, int C, int inPitch)
{
    long long i = (long long)blockIdx.x * blockDim.x + threadIdx.x;
    int C8 = C >> 3;
    long long tot = (long long)Rpad * C8;
    if (i >= tot) return;
    int r = (int)(i / C8), c = ((int)(i % C8)) << 3;
    __align__(16) __half h[8];
    if (r < R) {
        float4 a = *(const float4*)&in[(size_t)r * inPitch + c];
        float4 b = *(const float4*)&in[(size_t)r * inPitch + c + 4];
        h[0]=__float2half(a.x); h[1]=__float2half(a.y); h[2]=__float2half(a.z); h[3]=__float2half(a.w);
        h[4]=__float2half(b.x); h[5]=__float2half(b.y); h[6]=__float2half(b.z); h[7]=__float2half(b.w);
    } else {
#pragma unroll
        for (int k = 0; k < 8; k++) h[k] = __float2half(0.f);
    }
    *(uint4*)&out[(size_t)r * C + c] = *(uint4*)h;
}

// merged down-weight conversion: [wq_down | wkv_down | wk_rope | pad], C=DIMM
__global__ void cvtW_down_k(const float* __restrict__ w1, const float* __restrict__ w2,
                            const float* __restrict__ w3, __half* __restrict__ out)
{
    long long i = (long long)blockIdx.x * blockDim.x + threadIdx.x;
    const int C8 = DIMM >> 3;
    long long tot = (long long)NDOWNP * C8;
    if (i >= tot) return;
    int r = (int)(i / C8), c = ((int)(i % C8)) << 3;
    const float* src = 0;
    if (r < QR)              src = w1 + (size_t)r * DIMM + c;
    else if (r < QR+KVR)     src = w2 + (size_t)(r-QR) * DIMM + c;
    else if (r < NDOWN)      src = w3 + (size_t)(r-QR-KVR) * DIMM + c;
    __align__(16) __half h[8];
    if (src) {
        float4 a = ((const float4*)src)[0], b = ((const float4*)src)[1];
        h[0]=__float2half(a.x); h[1]=__float2half(a.y); h[2]=__float2half(a.z); h[3]=__float2half(a.w);
        h[4]=__float2half(b.x); h[5]=__float2half(b.y); h[6]=__float2half(b.z); h[7]=__float2half(b.w);
    } else {
#pragma unroll
        for (int k = 0; k < 8; k++) h[k] = __float2half(0.f);
    }
    *(uint4*)&out[(size_t)r * DIMM + c] = *(uint4*)h;
}

// merged up-weight conversion: [wq_up(2048) | wq_rope(1024)], C=QR
__global__ void cvtW_up_k(const float* __restrict__ w1, const float* __restrict__ w2,
                          __half* __restrict__ out)
{
    long long i = (long long)blockIdx.x * blockDim.x + threadIdx.x;
    const int C8 = QR >> 3;
    long long tot = (long long)NUP * C8;
    if (i >= tot) return;
    int r = (int)(i / C8), c = ((int)(i % C8)) << 3;
    const float* src = (r < NH*DN) ? w1 + (size_t)r * QR + c
                                   : w2 + (size_t)(r - NH*DN) * QR + c;
    float4 a = ((const float4*)src)[0], b = ((const float4*)src)[1];
    __align__(16) __half h[8];
    h[0]=__float2half(a.x); h[1]=__float2half(a.y); h[2]=__float2half(a.z); h[3]=__float2half(a.w);
    h[4]=__float2half(b.x); h[5]=__float2half(b.y); h[6]=__float2half(b.z); h[7]=__float2half(b.w);
    *(uint4*)&out[(size_t)r * QR + c] = *(uint4*)h;
}

// ============================================================
// GEMM mainloop macro (R13 verified core); epilogue differs per kernel
// ============================================================
#define STAGES 3
#define STAGE_BYTES 32768
#define GEMM_SMEM (STAGES*STAGE_BYTES)

#define GEMM_MAINLOOP(ACC)                                                      \
    extern __shared__ __align__(16) char smem[];                                \
    const uint32_t sb = smem_u32(smem);                                         \
    const int m0 = blockIdx.y * 128, n0 = blockIdx.x * 128;                     \
    const int tid = threadIdx.x, lane = tid & 31;                               \
    const int wm = (tid >> 5) & 3;                                              \
    const int wn = tid >> 7;                                                    \
    float ACC[2][8][4];                                                         \
    _Pragma("unroll")                                                           \
    for (int i = 0; i < 2; i++)                                                 \
        _Pragma("unroll")                                                       \
        for (int j = 0; j < 8; j++)                                             \
            _Pragma("unroll")                                                   \
            for (int q = 0; q < 4; q++) ACC[i][j][q] = 0.f;                     \
    const int KT = K >> 6;                                                      \
    const __half* Ag0 = A + (size_t)m0 * K;                                     \
    const __half* Bg0 = B + (size_t)n0 * K;                                     \
    const int fr = tid >> 3;                                                    \
    const int fc = tid & 7;                                                     \
    auto fill = [&](int j){                                                     \
        uint32_t base = sb + (uint32_t)(j % STAGES) * STAGE_BYTES;              \
        int k0 = j << 6;                                                        \
        _Pragma("unroll")                                                       \
        for (int i = 0; i < 4; i++) {                                           \
            int r = fr + i * 32;                                                \
            CPA16(base + sw128(r, fc), Ag0 + (size_t)r * K + k0 + fc*8);        \
        }                                                                       \
        _Pragma("unroll")                                                       \
        for (int i = 0; i < 4; i++) {                                           \
            int r = fr + i * 32;                                                \
            CPA16(base + 16384u + sw128(r, fc), Bg0 + (size_t)r * K + k0 + fc*8);\
        }                                                                       \
        CPCOMMIT();                                                             \
    };                                                                          \
    fill(0);                                                                    \
    fill(1);                                                                    \
    const int a_row  = lane & 15;                                               \
    const int a_ch   = lane >> 4;                                               \
    const int b_nrow = (lane & 7) + ((lane & 16) ? 8 : 0);                      \
    const int b_ch   = (lane >> 3) & 1;                                         \
    for (int kt = 0; kt < KT; kt++) {                                           \
        CPWAIT(1);                                                              \
        __syncthreads();                                                        \
        if (kt + 2 < KT) fill(kt + 2);                                          \
        else CPCOMMIT();                                                        \
        uint32_t aT = sb + (uint32_t)(kt % STAGES) * STAGE_BYTES;               \
        uint32_t bT = aT + 16384u;                                              \
        _Pragma("unroll")                                                       \
        for (int ks = 0; ks < 4; ks++) {                                        \
            uint32_t a[2][4];                                                   \
            _Pragma("unroll")                                                   \
            for (int i = 0; i < 2; i++)                                         \
                ldsm4(a[i], aT + sw128(wm*32 + i*16 + a_row, ks*2 + a_ch));     \
            uint32_t b[4][4];                                                   \
            _Pragma("unroll")                                                   \
            for (int g = 0; g < 4; g++)                                         \
                ldsm4(b[g], bT + sw128(wn*64 + g*16 + b_nrow, ks*2 + b_ch));    \
            _Pragma("unroll")                                                   \
            for (int i = 0; i < 2; i++)                                         \
                _Pragma("unroll")                                               \
                for (int g = 0; g < 4; g++) {                                   \
                    mma16816(ACC[i][2*g],   a[i], b[g][0], b[g][1]);            \
                    mma16816(ACC[i][2*g+1], a[i], b[g][2], b[g][3]);            \
                }                                                               \
        }                                                                       \
    }

// ---- fp32-out GEMM ----
__global__ __launch_bounds__(256, 2) void gemm_f32(
    const __half* __restrict__ A, const __half* __restrict__ B,
    float* __restrict__ C, int M, int N, int K)
{
    GEMM_MAINLOOP(acc)
    const int rb = m0 + wm*32;
    const int cb = n0 + wn*64;
#pragma unroll
    for (int i = 0; i < 2; i++)
#pragma unroll
        for (int j = 0; j < 8; j++) {
            int c = cb + j*8 + (lane & 3)*2;
            if (c < N) {
                int r = rb + i*16 + (lane >> 2);
                *(float2*)&C[(size_t)r * N + c]     = make_float2(acc[i][j][0], acc[i][j][1]);
                *(float2*)&C[(size_t)(r+8) * N + c] = make_float2(acc[i][j][2], acc[i][j][3]);
            }
        }
}

// ---- fp16-out GEMM (for kv_up) ----
__global__ __launch_bounds__(256, 2) void gemm_f16(
    const __half* __restrict__ A, const __half* __restrict__ B,
    __half* __restrict__ C, int M, int N, int K)
{
    GEMM_MAINLOOP(acc)
    const int rb = m0 + wm*32;
    const int cb = n0 + wn*64;
#pragma unroll
    for (int i = 0; i < 2; i++)
#pragma unroll
        for (int j = 0; j < 8; j++) {
            int c = cb + j*8 + (lane & 3)*2;
            if (c < N) {
                int r = rb + i*16 + (lane >> 2);
                *(uint32_t*)&C[(size_t)r * N + c]     = pack2h(acc[i][j][0], acc[i][j][1]);
                *(uint32_t*)&C[(size_t)(r+8) * N + c] = pack2h(acc[i][j][2], acc[i][j][3]);
            }
        }
}

// ---- up-proj GEMM with fused scale + RoPE + 2-term split pack into qsp ----
__global__ __launch_bounds__(256, 2) void gemm_qpack(
    const __half* __restrict__ A, const __half* __restrict__ B,
    __half* __restrict__ Q, int M, int N, int K)
{
    GEMM_MAINLOOP(acc)
    const int rb = m0 + wm*32;
    const int cb = n0 + wn*64;
    const float scale = 0.072168783648703220563f;   // 1/sqrt(192)
#pragma unroll
    for (int i = 0; i < 2; i++)
#pragma unroll
        for (int j = 0; j < 8; j++) {
            int c = cb + j*8 + (lane & 3)*2;
#pragma unroll
            for (int half = 0; half < 2; half++) {
                int r = rb + i*16 + (lane >> 2) + half*8;
                float v0 = acc[i][j][half*2], v1 = acc[i][j][half*2+1];
                int b = r >> 11;            // r / SS
                int s = r & (SS-1);
                int h, d;
                float o0, o1;
                if (c < 2048) {
                    h = c >> 7; d = c & 127;
                    o0 = v0 * scale; o1 = v1 * scale;
                } else {
                    int cc = c - 2048;
                    h = cc >> 6;
                    int pd = cc & 63;
                    int p = pd >> 1;
                    float inv = powf(10000.f, (-2.0f * (float)p) / 64.f);
                    float sn, cs;
                    sincosf((float)s * inv, &sn, &cs);
                    o0 = (v0 * cs - v1 * sn) * scale;
                    o1 = (v0 * sn + v1 * cs) * scale;
                    d = 128 + pd;
                }
                size_t base = ((size_t)(b*NH + h) * SS + s) * 384;
                __half h0 = __float2half(o0), h1 = __float2half(o1);
                float  l0f = o0 - __half2float(h0), l1f = o1 - __half2float(h1);
                *(uint32_t*)&Q[base + d]       = (uint32_t)(*(uint16_t*)&h0) | ((uint32_t)(*(uint16_t*)&h1) << 16);
                *(uint32_t*)&Q[base + 192 + d] = pack2h(l0f, l1f);
            }
        }
}

// ---------------- RMSNorm -> fp16 hi-only (R13, verified) ----------------
__global__ void rmsnorm_h_k(const float* __restrict__ x, const float* __restrict__ w,
                            __half* __restrict__ out, int W, int pitch)
{
    const int row = blockIdx.x;
    const float* xr = x + (size_t)row * pitch;
    const float4* x4 = (const float4*)xr;
    float ss = 0.f;
    int W4 = W >> 2;
    for (int i = threadIdx.x; i < W4; i += blockDim.x) {
        float4 v = x4[i];
        ss += v.x*v.x + v.y*v.y + v.z*v.z + v.w*v.w;
    }
    __shared__ float red[32];
#pragma unroll
    for (int o = 16; o; o >>= 1) ss += __shfl_down_sync(0xffffffffu, ss, o);
    if ((threadIdx.x & 31) == 0) red[threadIdx.x >> 5] = ss;
    __syncthreads();
    if (threadIdx.x < 32) {
        float v = (threadIdx.x < (blockDim.x >> 5)) ? red[threadIdx.x] : 0.f;
#pragma unroll
        for (int o = 16; o; o >>= 1) v += __shfl_down_sync(0xffffffffu, v, o);
        if (threadIdx.x == 0) red[0] = rsqrtf(v / (float)W + 1e-6f);
    }
    __syncthreads();
    float r = red[0];
    __half* orow = out + (size_t)row * W;
    const float4* w4 = (const float4*)w;
    int W8 = W >> 3;
    for (int i8 = threadIdx.x; i8 < W8; i8 += blockDim.x) {
        float4 a = x4[i8*2], b = x4[i8*2+1];
        float4 wa = w4[i8*2], wb = w4[i8*2+1];
        __align__(16) __half h[8];
        h[0]=__float2half(a.x*r*wa.x); h[1]=__float2half(a.y*r*wa.y);
        h[2]=__float2half(a.z*r*wa.z); h[3]=__float2half(a.w*r*wa.w);
        h[4]=__float2half(b.x*r*wb.x); h[5]=__float2half(b.y*r*wb.y);
        h[6]=__float2half(b.z*r*wb.z); h[7]=__float2half(b.w*r*wb.w);
        *(uint4*)&orow[i8*8] = *(uint4*)h;
    }
}

// ---------------- RoPE on k_rope slice of dall ----------------
__global__ void rope_k(float* __restrict__ x, int pitch, int colOff,
                       int nheads, int d, int total_pairs)
{
    int idx = blockIdx.x * blockDim.x + threadIdx.x;
    if (idx >= total_pairs) return;
    int pairs_per_row = nheads * (d / 2);
    int row = idx / pairs_per_row;
    int p   = idx % pairs_per_row;
    int h = p / (d / 2);
    int i = p % (d / 2);
    int pos = row % SS;
    float inv = powf(10000.f, (-2.0f * (float)i) / (float)d);
    float ang = (float)pos * inv;
    float s, c;
    sincosf(ang, &s, &c);
    float* base = x + (size_t)row * pitch + colOff + h * d + 2 * i;
    float x1 = base[0], x2 = base[1];
    base[0] = x1 * c - x2 * s;
    base[1] = x1 * s + x2 * c;
}

// ---------------- pack K (kv now fp16) ----------------
__global__ void pack_k(const __half* __restrict__ kv16, const float* __restrict__ dall,
                       __half* __restrict__ out)
{
    long long idx = (long long)blockIdx.x * blockDim.x + threadIdx.x;
    if (idx >= (long long)BB*NH*SS*24) return;
    int c8 = (int)(idx % 24);
    int s  = (int)((idx / 24) % SS);
    int bh = (int)(idx / (24LL*SS));
    int b = bh / NH, h = bh % NH;
    size_t m = (size_t)b * SS + s;
    int d = c8 * 8;
    if (d < 128) {
        uint4 v = *(const uint4*)&kv16[m * (NH*256) + h*256 + d];
        *(uint4*)&out[((size_t)bh * SS + s) * 192 + d] = v;
    } else {
        const float* src = &dall[m * NDOWN + 2048 + (d - 128)];
        float4 a = ((const float4*)src)[0], bb = ((const float4*)src)[1];
        __align__(16) __half hh[8];
        hh[0]=__float2half(a.x);  hh[1]=__float2half(a.y);  hh[2]=__float2half(a.z);  hh[3]=__float2half(a.w);
        hh[4]=__float2half(bb.x); hh[5]=__float2half(bb.y); hh[6]=__float2half(bb.z); hh[7]=__float2half(bb.w);
        *(uint4*)&out[((size_t)bh * SS + s) * 192 + d] = *(uint4*)hh;
    }
}

// ---------------- pack V transpose (kv now fp16) ----------------
__global__ __launch_bounds__(256) void pack_v(const __half* __restrict__ kv16,
                                              __half* __restrict__ vt)
{
    __shared__ float vs[64][129];
    const int t = blockIdx.x, h = blockIdx.y, b = blockIdx.z;
    const int bh = b*NH + h;
    const int tid = threadIdx.x;
    for (int i = tid; i < 64*16; i += 256) {
        int r = i >> 4, d8 = (i & 15) * 8;
        size_t m = (size_t)b * SS + t*64 + r;
        uint4 raw = *(const uint4*)&kv16[m * (NH*256) + h*256 + 128 + d8];
        const __half* hp = (const __half*)&raw;
#pragma unroll
        for (int k = 0; k < 8; k++) vs[r][d8 + k] = __half2float(hp[k]);
    }
    __syncthreads();
    for (int i = tid; i < 128*8; i += 256) {
        int d = i >> 3, w8 = i & 7;
        int kk0 = w8 * 8;
        __align__(16) __half p[8];
#pragma unroll
        for (int k = 0; k < 8; k++) p[k] = __float2half(vs[kk0 + k][d]);
        *(uint4*)&vt[((size_t)bh * 128 + d) * SS + t*64 + kk0] = *(uint4*)p;
    }
}

// ============================================================
// HMMA flash attention — Q resident (R10/R13 core, verified)
// ============================================================
#define KBASE 49152u
#define VBASE 73728u
#define PBASE 90112u
#define ATT_SMEM 108544

__global__ __launch_bounds__(256, 2) void attn_mma(
    const __half* __restrict__ Qsp, const __half* __restrict__ Ksp,
    const __half* __restrict__ Vt, __half* __restrict__ ats)
{
    extern __shared__ __align__(16) char smem[];
    const uint32_t sb = smem_u32(smem);
    const int qt = (int)gridDim.x - 1 - (int)blockIdx.x;
    const int h = blockIdx.y, b = blockIdx.z;
    const int bh = b*NH + h;
    const int q0 = qt * 64;
    const int tid = threadIdx.x, lane = tid & 31;
    const int wm = (tid >> 5) & 3, wn = tid >> 7;

    const __half* Qg = Qsp + ((size_t)bh * SS + q0) * 384;
    const __half* Kg = Ksp + (size_t)bh * SS * 192;
    const __half* Vg = Vt  + (size_t)bh * 128 * SS;

    float* redmax = (float*)(smem + 107520);
    float* redsum = (float*)(smem + 108032);

    {
        int r = tid >> 3, ch = tid & 7;
#pragma unroll
        for (int cq = 0; cq < 6; cq++) {
#pragma unroll
            for (int it = 0; it < 2; it++) {
                int rr = r + it*32;
                CPA16(sb + (uint32_t)cq*8192u + sw128(rr, ch),
                      Qg + (size_t)rr*384 + cq*64 + ch*8);
            }
        }
        CPCOMMIT();
    }

    float acc_o[8][4];
#pragma unroll
    for (int i = 0; i < 8; i++)
#pragma unroll
        for (int j = 0; j < 4; j++) acc_o[i][j] = 0.f;
    float m0 = -1e30f, m1 = -1e30f, l0 = 0.f, l1 = 0.f;

    const int a_row  = lane & 15;
    const int a_ch   = lane >> 4;
    const int b_nrow = (lane & 7) + ((lane & 16) ? 8 : 0);
    const int b_ch   = (lane >> 3) & 1;
    const int r0 = wm*16 + (lane >> 2);

    for (int t = 0; t <= qt; t++) {
        const int k0 = t * 64;
        {
            int r = tid >> 3, ch = tid & 7;
#pragma unroll
            for (int slot = 0; slot < 2; slot++) {
#pragma unroll
                for (int it = 0; it < 2; it++) {
                    int rr = r + it*32;
                    CPA16(sb + KBASE + (uint32_t)slot*8192u + sw128(rr, ch),
                          Kg + (size_t)(k0 + rr)*192 + slot*64 + ch*8);
                }
                CPCOMMIT();
            }
#pragma unroll
            for (int it = 0; it < 4; it++) {
                int i = tid + it*256;
                int d = i >> 3, vch = i & 7;
                CPA16(sb + VBASE + sw128(d, vch), Vg + (size_t)d*SS + t*64 + vch*8);
            }
            CPCOMMIT();
        }

        float acc_s[4][4];
#pragma unroll
        for (int i = 0; i < 4; i++)
#pragma unroll
            for (int j = 0; j < 4; j++) acc_s[i][j] = 0.f;

#pragma unroll
        for (int c = 0; c < 3; c++) {
            if (c < 2) { CPWAIT(2); } else { CPWAIT(0); }
            __syncthreads();
            if (c == 0) {
                int r = tid >> 3, ch = tid & 7;
#pragma unroll
                for (int it = 0; it < 2; it++) {
                    int rr = r + it*32;
                    CPA16(sb + KBASE + 2u*8192u + sw128(rr, ch),
                          Kg + (size_t)(k0 + rr)*192 + 2*64 + ch*8);
                }
                CPCOMMIT();
            }
            uint32_t kb = sb + KBASE + (uint32_t)c*8192u;
            uint32_t qh = sb + (uint32_t)c*8192u;
            uint32_t ql = sb + (uint32_t)(c+3)*8192u;
#pragma unroll
            for (int ks = 0; ks < 4; ks++) {
                uint32_t a0[4], a1[4];
                ldsm4(a0, qh + sw128(wm*16 + a_row, ks*2 + a_ch));
                ldsm4(a1, ql + sw128(wm*16 + a_row, ks*2 + a_ch));
#pragma unroll
                for (int g = 0; g < 2; g++) {
                    uint32_t bb[4];
                    ldsm4(bb, kb + sw128(wn*32 + g*16 + b_nrow, ks*2 + b_ch));
                    mma16816(acc_s[g*2],   a0, bb[0], bb[1]);
                    mma16816(acc_s[g*2+1], a0, bb[2], bb[3]);
                    mma16816(acc_s[g*2],   a1, bb[0], bb[1]);
                    mma16816(acc_s[g*2+1], a1, bb[2], bb[3]);
                }
            }
        }

        if (t == qt) {
#pragma unroll
            for (int nt = 0; nt < 4; nt++) {
                int colb = wn*32 + nt*8 + (lane & 3)*2;
                if (colb     > r0)     acc_s[nt][0] = -1e30f;
                if (colb + 1 > r0)     acc_s[nt][1] = -1e30f;
                if (colb     > r0 + 8) acc_s[nt][2] = -1e30f;
                if (colb + 1 > r0 + 8) acc_s[nt][3] = -1e30f;
            }
        }

        float mx0 = -1e30f, mx1 = -1e30f;
#pragma unroll
        for (int nt = 0; nt < 4; nt++) {
            mx0 = fmaxf(mx0, fmaxf(acc_s[nt][0], acc_s[nt][1]));
            mx1 = fmaxf(mx1, fmaxf(acc_s[nt][2], acc_s[nt][3]));
        }
        mx0 = fmaxf(mx0, __shfl_xor_sync(0xffffffffu, mx0, 1));
        mx0 = fmaxf(mx0, __shfl_xor_sync(0xffffffffu, mx0, 2));
        mx1 = fmaxf(mx1, __shfl_xor_sync(0xffffffffu, mx1, 1));
        mx1 = fmaxf(mx1, __shfl_xor_sync(0xffffffffu, mx1, 2));
        if ((lane & 3) == 0) {
            redmax[wn*64 + r0]     = mx0;
            redmax[wn*64 + r0 + 8] = mx1;
        }
        __syncthreads();
        float tm0 = fmaxf(mx0, redmax[(wn^1)*64 + r0]);
        float tm1 = fmaxf(mx1, redmax[(wn^1)*64 + r0 + 8]);
        float nm0 = fmaxf(m0, tm0), nm1 = fmaxf(m1, tm1);
        float f0 = __expf(m0 - nm0), f1 = __expf(m1 - nm1);

        float s0 = 0.f, s1 = 0.f;
#pragma unroll
        for (int nt = 0; nt < 4; nt++) {
            acc_s[nt][0] = __expf(acc_s[nt][0] - nm0);
            acc_s[nt][1] = __expf(acc_s[nt][1] - nm0);
            acc_s[nt][2] = __expf(acc_s[nt][2] - nm1);
            acc_s[nt][3] = __expf(acc_s[nt][3] - nm1);
            s0 += acc_s[nt][0] + acc_s[nt][1];
            s1 += acc_s[nt][2] + acc_s[nt][3];
        }
        s0 += __shfl_xor_sync(0xffffffffu, s0, 1);
        s0 += __shfl_xor_sync(0xffffffffu, s0, 2);
        s1 += __shfl_xor_sync(0xffffffffu, s1, 1);
        s1 += __shfl_xor_sync(0xffffffffu, s1, 2);
        if ((lane & 3) == 0) {
            redsum[wn*64 + r0]     = s0;
            redsum[wn*64 + r0 + 8] = s1;
        }
        {
            char* P = smem + PBASE;
            int colb = wn*32 + (lane & 3)*2;
#pragma unroll
            for (int nt = 0; nt < 4; nt++) {
                int col = colb + nt*8;
#pragma unroll
                for (int half = 0; half < 2; half++) {
                    float pa = acc_s[nt][half*2], pb = acc_s[nt][half*2+1];
                    int row = r0 + half*8;
                    __half ha = __float2half(pa), hb = __float2half(pb);
                    float la = pa - __half2float(ha), lb = pb - __half2float(hb);
                    uint32_t hi = (uint32_t)(*(uint16_t*)&ha) | ((uint32_t)(*(uint16_t*)&hb) << 16);
                    uint32_t lo = pack2h(la, lb);
                    uint32_t* base = (uint32_t*)(P + row*272 + col*2);
                    base[0]  = hi;
                    base[32] = lo;
                }
            }
        }
        __syncthreads();
        float ts0 = s0 + redsum[(wn^1)*64 + r0];
        float ts1 = s1 + redsum[(wn^1)*64 + r0 + 8];
        l0 = l0 * f0 + ts0;
        l1 = l1 * f1 + ts1;
        m0 = nm0; m1 = nm1;
#pragma unroll
        for (int nt = 0; nt < 8; nt++) {
            acc_o[nt][0] *= f0; acc_o[nt][1] *= f0;
            acc_o[nt][2] *= f1; acc_o[nt][3] *= f1;
        }

#pragma unroll
        for (int pc = 0; pc < 2; pc++) {
            uint32_t pseg = (uint32_t)pc * 128u;
#pragma unroll
            for (int ks = 0; ks < 4; ks++) {
                uint32_t a[4];
                ldsm4(a, sb + PBASE + (uint32_t)((wm*16 + a_row)*272) + pseg
                         + (uint32_t)(ks*32 + a_ch*16));
#pragma unroll
                for (int g = 0; g < 4; g++) {
                    uint32_t bb[4];
                    ldsm4(bb, sb + VBASE + sw128(wn*64 + g*16 + b_nrow, ks*2 + b_ch));
                    mma16816(acc_o[g*2],   a, bb[0], bb[1]);
                    mma16816(acc_o[g*2+1], a, bb[2], bb[3]);
                }
            }
        }
        __syncthreads();
    }

    float il0 = 1.f / l0, il1 = 1.f / l1;
    size_t mrow0 = (size_t)b * SS + q0 + r0;
#pragma unroll
    for (int nt = 0; nt < 8; nt++) {
        int col = h*128 + wn*64 + nt*8 + (lane & 3)*2;
#pragma unroll
        for (int half = 0; half < 2; half++) {
            float oa = acc_o[nt][half*2]   * (half ? il1 : il0);
            float ob = acc_o[nt][half*2+1] * (half ? il1 : il0);
            size_t row = mrow0 + half*8;
            ((uint32_t*)(ats + row * 2048))[col >> 1] = pack2h(oa, ob);
        }
    }
}

// ---------------- host orchestration ----------------
static void convB(const float* in, __half* out, int R, int Rpad, int C, int inPitch)
{
    long long tot = (long long)Rpad * (C >> 3);
    cvtB_k<<<(int)((tot + 255) / 256), 256>>>(in, out, R, Rpad, C, inPitch);
}

extern "C" void kernel_launch(void* const* d_in, const int* in_sizes, int n_in,
                              void* d_out, int out_size)
{
    const float* x        = (const float*)d_in[0];
    const float* wq_down  = (const float*)d_in[1];
    const float* q_norm_w = (const float*)d_in[2];
    const float* wq_up    = (const float*)d_in[3];
    const float* wq_rope  = (const float*)d_in[4];
    const float* wkv_down = (const float*)d_in[5];
    const float* kv_norm_w= (const float*)d_in[6];
    const float* wkv_up   = (const float*)d_in[7];
    const float* wk_rope  = (const float*)d_in[8];
    const float* wo       = (const float*)d_in[9];
    float* out = (float*)d_out;

    float* dall;
    cudaGetSymbolAddress((void**)&dall, g_dall);

    __half *xs, *wdall, *qcs, *wuall, *kvcs, *wkvu, *kvu16, *ats, *wos, *qsp, *ksp, *vt;
    cudaGetSymbolAddress((void**)&xs,    g_xs);
    cudaGetSymbolAddress((void**)&wdall, g_wdall);
    cudaGetSymbolAddress((void**)&qcs,   g_qcs);
    cudaGetSymbolAddress((void**)&wuall, g_wuall);
    cudaGetSymbolAddress((void**)&kvcs,  g_kvcs);
    cudaGetSymbolAddress((void**)&wkvu,  g_wkvu);
    cudaGetSymbolAddress((void**)&kvu16, g_kvu16);
    cudaGetSymbolAddress((void**)&ats,   g_ats);
    cudaGetSymbolAddress((void**)&wos,   g_wos);
    cudaGetSymbolAddress((void**)&qsp,   g_qsp);
    cudaGetSymbolAddress((void**)&ksp,   g_ksp);
    cudaGetSymbolAddress((void**)&vt,    g_vt);

    cudaFuncSetAttribute(gemm_f32,   cudaFuncAttributeMaxDynamicSharedMemorySize, GEMM_SMEM);
    cudaFuncSetAttribute(gemm_f16,   cudaFuncAttributeMaxDynamicSharedMemorySize, GEMM_SMEM);
    cudaFuncSetAttribute(gemm_qpack, cudaFuncAttributeMaxDynamicSharedMemorySize, GEMM_SMEM);

    // ---- stage 1: merged down projection ----
    convB(x, xs, MT, MT, DIMM, DIMM);
    {
        long long tot = (long long)NDOWNP * (DIMM >> 3);
        cvtW_down_k<<<(int)((tot + 255) / 256), 256>>>(wq_down, wkv_down, wk_rope, wdall);
    }
    gemm_f32<<<dim3((NDOWN + 127)/128, MT/128), 256, GEMM_SMEM>>>(xs, wdall, dall, MT, NDOWN, DIMM);

    // ---- rmsnorm -> fp16 hi; kr rope ----
    rmsnorm_h_k<<<MT, 256>>>(dall,      q_norm_w,  qcs,  QR,  NDOWN);
    rmsnorm_h_k<<<MT, 256>>>(dall + QR, kv_norm_w, kvcs, KVR, NDOWN);
    rope_k<<<(MT*32 + 255)/256, 256>>>(dall, NDOWN, QR+KVR, 1, DR, MT*32);

    // ---- stage 2: up projections ----
    {
        long long tot = (long long)NUP * (QR >> 3);
        cvtW_up_k<<<(int)((tot + 255) / 256), 256>>>(wq_up, wq_rope, wuall);
    }
    gemm_qpack<<<dim3(NUP/128, MT/128), 256, GEMM_SMEM>>>(qcs, wuall, qsp, MT, NUP, QR);
    convB(wkv_up, wkvu, NH*(DN+DVV), NH*(DN+DVV), KVR, KVR);
    gemm_f16<<<dim3((NH*(DN+DVV))/128, MT/128), 256, GEMM_SMEM>>>(kvcs, wkvu, kvu16, MT, NH*(DN+DVV), KVR);

    // ---- packs ----
    {
        long long tot = (long long)BB*NH*SS*24;
        pack_k<<<(int)((tot + 255) / 256), 256>>>(kvu16, dall, ksp);
    }
    pack_v<<<dim3(SS/64, NH, BB), 256>>>(kvu16, vt);

    // ---- HMMA flash attention ----
    cudaFuncSetAttribute(attn_mma, cudaFuncAttributeMaxDynamicSharedMemorySize, ATT_SMEM);
    attn_mma<<<dim3(SS/64, NH, BB), 256, ATT_SMEM>>>(qsp, ksp, vt, ats);

    // ---- output projection ----
    convB(wo, wos, DIMM, DIMM, NH*DVV, NH*DVV);
    gemm_f32<<<dim3((DIMM + 127)/128, MT/128), 256, GEMM_SMEM>>>(ats, wos, out, MT, DIMM, NH*DVV);
}

// round 15
// speedup vs baseline: 1.4609x; 1.0713x over previous
#include <cuda_runtime.h>
#include <cuda_fp16.h>
#include <math.h>
#include <stdint.h>

#define BB 2
#define SS 2048
#define DIMM 2048
#define NH 16
#define QR 1536
#define KVR 512
#define DN 128
#define DR 64
#define DVV 128
#define MT (BB*SS)

#define NDOWN 2112
#define NDOWNP 2176
#define NUP 3072

// ---------------- fp32 scratch ----------------
__device__ float g_dall[MT*NDOWN];

// ---------------- fp16 scratch ----------------
__device__ __half g_xs   [MT    * DIMM];
__device__ __half g_wdall[NDOWNP* DIMM];
__device__ __half g_qcs  [MT    * QR];
__device__ __half g_wuall[NUP   * QR];
__device__ __half g_kvcs [MT    * KVR];
__device__ __half g_wkvu [(NH*(DN+DVV)) * KVR];
__device__ __half g_kvu16[MT    * (NH*(DN+DVV))];   // only V half valid
__device__ __half g_ats  [MT    * (NH*DVV)];
__device__ __half g_wos  [DIMM  * (NH*DVV)];

// ---------------- attention packed operands ----------------
__device__ __half g_qsp[BB*NH*SS*384];     // [bh][s][Qh|Ql]
__device__ __half g_ksp[BB*NH*SS*192];     // [bh][s][Kh]
__device__ __half g_vt [BB*NH*128*SS];     // [bh][d][s]

// ============================================================
// helpers
// ============================================================
__device__ __forceinline__ uint32_t smem_u32(const void* p){
    uint32_t a;
    asm("{ .reg .u64 t; cvta.to.shared.u64 t, %1; cvt.u32.u64 %0, t; }" : "=r"(a) : "l"(p));
    return a;
}
#define CPA16(dst, src) asm volatile("cp.async.cg.shared.global [%0], [%1], 16;" :: "r"(dst), "l"(src))
#define CPCOMMIT()      asm volatile("cp.async.commit_group;")
#define CPWAIT(n)       asm volatile("cp.async.wait_group %0;" :: "n"(n))

__device__ __forceinline__ void ldsm4(uint32_t* r, uint32_t addr){
    asm volatile("ldmatrix.sync.aligned.m8n8.x4.shared.b16 {%0,%1,%2,%3}, [%4];"
        : "=r"(r[0]), "=r"(r[1]), "=r"(r[2]), "=r"(r[3]) : "r"(addr));
}
__device__ __forceinline__ void mma16816(float* c, const uint32_t* a, uint32_t b0, uint32_t b1){
    asm volatile("mma.sync.aligned.m16n8k16.row.col.f32.f16.f16.f32 "
        "{%0,%1,%2,%3}, {%4,%5,%6,%7}, {%8,%9}, {%0,%1,%2,%3};"
        : "+f"(c[0]), "+f"(c[1]), "+f"(c[2]), "+f"(c[3])
        : "r"(a[0]), "r"(a[1]), "r"(a[2]), "r"(a[3]), "r"(b0), "r"(b1));
}
__device__ __forceinline__ uint32_t sw128(int row, int chunk){
    return (uint32_t)(row * 128 + ((chunk ^ (row & 7)) * 16));
}
__device__ __forceinline__ uint32_t pack2h(float a, float b){
    __half ha = __float2half(a), hb = __float2half(b);
    return (uint32_t)(*(uint16_t*)&ha) | ((uint32_t)(*(uint16_t*)&hb) << 16);
}

// ============================================================
// conversions
// ============================================================
__global__ void cvtB_k(const float* __restrict__ in, __half* __restrict__ out,
                       int R, int Rpad, int C, int inPitch)
{
    long long i = (long long)blockIdx.x * blockDim.x + threadIdx.x;
    int C8 = C >> 3;
    long long tot = (long long)Rpad * C8;
    if (i >= tot) return;
    int r = (int)(i / C8), c = ((int)(i % C8)) << 3;
    __align__(16) __half h[8];
    if (r < R) {
        float4 a = *(const float4*)&in[(size_t)r * inPitch + c];
        float4 b = *(const float4*)&in[(size_t)r * inPitch + c + 4];
        h[0]=__float2half(a.x); h[1]=__float2half(a.y); h[2]=__float2half(a.z); h[3]=__float2half(a.w);
        h[4]=__float2half(b.x); h[5]=__float2half(b.y); h[6]=__float2half(b.z); h[7]=__float2half(b.w);
    } else {
#pragma unroll
        for (int k = 0; k < 8; k++) h[k] = __float2half(0.f);
    }
    *(uint4*)&out[(size_t)r * C + c] = *(uint4*)h;
}

__global__ void cvtW_down_k(const float* __restrict__ w1, const float* __restrict__ w2,
                            const float* __restrict__ w3, __half* __restrict__ out)
{
    long long i = (long long)blockIdx.x * blockDim.x + threadIdx.x;
    const int C8 = DIMM >> 3;
    long long tot = (long long)NDOWNP * C8;
    if (i >= tot) return;
    int r = (int)(i / C8), c = ((int)(i % C8)) << 3;
    const float* src = 0;
    if (r < QR)              src = w1 + (size_t)r * DIMM + c;
    else if (r < QR+KVR)     src = w2 + (size_t)(r-QR) * DIMM + c;
    else if (r < NDOWN)      src = w3 + (size_t)(r-QR-KVR) * DIMM + c;
    __align__(16) __half h[8];
    if (src) {
        float4 a = ((const float4*)src)[0], b = ((const float4*)src)[1];
        h[0]=__float2half(a.x); h[1]=__float2half(a.y); h[2]=__float2half(a.z); h[3]=__float2half(a.w);
        h[4]=__float2half(b.x); h[5]=__float2half(b.y); h[6]=__float2half(b.z); h[7]=__float2half(b.w);
    } else {
#pragma unroll
        for (int k = 0; k < 8; k++) h[k] = __float2half(0.f);
    }
    *(uint4*)&out[(size_t)r * DIMM + c] = *(uint4*)h;
}

__global__ void cvtW_up_k(const float* __restrict__ w1, const float* __restrict__ w2,
                          __half* __restrict__ out)
{
    long long i = (long long)blockIdx.x * blockDim.x + threadIdx.x;
    const int C8 = QR >> 3;
    long long tot = (long long)NUP * C8;
    if (i >= tot) return;
    int r = (int)(i / C8), c = ((int)(i % C8)) << 3;
    const float* src = (r < NH*DN) ? w1 + (size_t)r * QR + c
                                   : w2 + (size_t)(r - NH*DN) * QR + c;
    float4 a = ((const float4*)src)[0], b = ((const float4*)src)[1];
    __align__(16) __half h[8];
    h[0]=__float2half(a.x); h[1]=__float2half(a.y); h[2]=__float2half(a.z); h[3]=__float2half(a.w);
    h[4]=__float2half(b.x); h[5]=__float2half(b.y); h[6]=__float2half(b.z); h[7]=__float2half(b.w);
    *(uint4*)&out[(size_t)r * QR + c] = *(uint4*)h;
}

// ============================================================
// GEMM mainloop macro (verified core)
// ============================================================
#define STAGES 3
#define STAGE_BYTES 32768
#define GEMM_SMEM (STAGES*STAGE_BYTES)

#define GEMM_MAINLOOP(ACC)                                                      \
    extern __shared__ __align__(16) char smem[];                                \
    const uint32_t sb = smem_u32(smem);                                         \
    const int m0 = blockIdx.y * 128, n0 = blockIdx.x * 128;                     \
    const int tid = threadIdx.x, lane = tid & 31;                               \
    const int wm = (tid >> 5) & 3;                                              \
    const int wn = tid >> 7;                                                    \
    float ACC[2][8][4];                                                         \
    _Pragma("unroll")                                                           \
    for (int i = 0; i < 2; i++)                                                 \
        _Pragma("unroll")                                                       \
        for (int j = 0; j < 8; j++)                                             \
            _Pragma("unroll")                                                   \
            for (int q = 0; q < 4; q++) ACC[i][j][q] = 0.f;                     \
    const int KT = K >> 6;                                                      \
    const __half* Ag0 = A + (size_t)m0 * K;                                     \
    const __half* Bg0 = B + (size_t)n0 * K;                                     \
    const int fr = tid >> 3;                                                    \
    const int fc = tid & 7;                                                     \
    auto fill = [&](int j){                                                     \
        uint32_t base = sb + (uint32_t)(j % STAGES) * STAGE_BYTES;              \
        int k0 = j << 6;                                                        \
        _Pragma("unroll")                                                       \
        for (int i = 0; i < 4; i++) {                                           \
            int r = fr + i * 32;                                                \
            CPA16(base + sw128(r, fc), Ag0 + (size_t)r * K + k0 + fc*8);        \
        }                                                                       \
        _Pragma("unroll")                                                       \
        for (int i = 0; i < 4; i++) {                                           \
            int r = fr + i * 32;                                                \
            CPA16(base + 16384u + sw128(r, fc), Bg0 + (size_t)r * K + k0 + fc*8);\
        }                                                                       \
        CPCOMMIT();                                                             \
    };                                                                          \
    fill(0);                                                                    \
    fill(1);                                                                    \
    const int a_row  = lane & 15;                                               \
    const int a_ch   = lane >> 4;                                               \
    const int b_nrow = (lane & 7) + ((lane & 16) ? 8 : 0);                      \
    const int b_ch   = (lane >> 3) & 1;                                         \
    for (int kt = 0; kt < KT; kt++) {                                           \
        CPWAIT(1);                                                              \
        __syncthreads();                                                        \
        if (kt + 2 < KT) fill(kt + 2);                                          \
        else CPCOMMIT();                                                        \
        uint32_t aT = sb + (uint32_t)(kt % STAGES) * STAGE_BYTES;               \
        uint32_t bT = aT + 16384u;                                              \
        _Pragma("unroll")                                                       \
        for (int ks = 0; ks < 4; ks++) {                                        \
            uint32_t a[2][4];                                                   \
            _Pragma("unroll")                                                   \
            for (int i = 0; i < 2; i++)                                         \
                ldsm4(a[i], aT + sw128(wm*32 + i*16 + a_row, ks*2 + a_ch));     \
            uint32_t b[4][4];                                                   \
            _Pragma("unroll")                                                   \
            for (int g = 0; g < 4; g++)                                         \
                ldsm4(b[g], bT + sw128(wn*64 + g*16 + b_nrow, ks*2 + b_ch));    \
            _Pragma("unroll")                                                   \
            for (int i = 0; i < 2; i++)                                         \
                _Pragma("unroll")                                               \
                for (int g = 0; g < 4; g++) {                                   \
                    mma16816(ACC[i][2*g],   a[i], b[g][0], b[g][1]);            \
                    mma16816(ACC[i][2*g+1], a[i], b[g][2], b[g][3]);            \
                }                                                               \
        }                                                                       \
    }

// ---- fp32-out GEMM ----
__global__ __launch_bounds__(256, 2) void gemm_f32(
    const __half* __restrict__ A, const __half* __restrict__ B,
    float* __restrict__ C, int M, int N, int K)
{
    GEMM_MAINLOOP(acc)
    const int rb = m0 + wm*32;
    const int cb = n0 + wn*64;
#pragma unroll
    for (int i = 0; i < 2; i++)
#pragma unroll
        for (int j = 0; j < 8; j++) {
            int c = cb + j*8 + (lane & 3)*2;
            if (c < N) {
                int r = rb + i*16 + (lane >> 2);
                *(float2*)&C[(size_t)r * N + c]     = make_float2(acc[i][j][0], acc[i][j][1]);
                *(float2*)&C[(size_t)(r+8) * N + c] = make_float2(acc[i][j][2], acc[i][j][3]);
            }
        }
}

// ---- kv-up GEMM: k_nope cols -> ksp directly; V cols -> kvu16 ----
__global__ __launch_bounds__(256, 2) void gemm_kvpack(
    const __half* __restrict__ A, const __half* __restrict__ B,
    __half* __restrict__ kvu16, __half* __restrict__ ksp, int M, int N, int K)
{
    GEMM_MAINLOOP(acc)
    const int rb = m0 + wm*32;
    const int cb = n0 + wn*64;
#pragma unroll
    for (int i = 0; i < 2; i++)
#pragma unroll
        for (int j = 0; j < 8; j++) {
            int c = cb + j*8 + (lane & 3)*2;
            int h = c >> 8, d = c & 255;
#pragma unroll
            for (int half = 0; half < 2; half++) {
                int r = rb + i*16 + (lane >> 2) + half*8;
                uint32_t val = pack2h(acc[i][j][half*2], acc[i][j][half*2+1]);
                if (d < 128) {
                    int b = r >> 11, s = r & (SS-1);
                    *(uint32_t*)&ksp[((size_t)(b*NH + h) * SS + s) * 192 + d] = val;
                } else {
                    *(uint32_t*)&kvu16[(size_t)r * (NH*256) + c] = val;
                }
            }
        }
}

// ---- up-proj GEMM with fused scale + RoPE + 2-term split pack into qsp ----
__global__ __launch_bounds__(256, 2) void gemm_qpack(
    const __half* __restrict__ A, const __half* __restrict__ B,
    __half* __restrict__ Q, int M, int N, int K)
{
    GEMM_MAINLOOP(acc)
    const int rb = m0 + wm*32;
    const int cb = n0 + wn*64;
    const float scale = 0.072168783648703220563f;
#pragma unroll
    for (int i = 0; i < 2; i++)
#pragma unroll
        for (int j = 0; j < 8; j++) {
            int c = cb + j*8 + (lane & 3)*2;
#pragma unroll
            for (int half = 0; half < 2; half++) {
                int r = rb + i*16 + (lane >> 2) + half*8;
                float v0 = acc[i][j][half*2], v1 = acc[i][j][half*2+1];
                int b = r >> 11;
                int s = r & (SS-1);
                int h, d;
                float o0, o1;
                if (c < 2048) {
                    h = c >> 7; d = c & 127;
                    o0 = v0 * scale; o1 = v1 * scale;
                } else {
                    int cc = c - 2048;
                    h = cc >> 6;
                    int pd = cc & 63;
                    int p = pd >> 1;
                    float inv = powf(10000.f, (-2.0f * (float)p) / 64.f);
                    float sn, cs;
                    sincosf((float)s * inv, &sn, &cs);
                    o0 = (v0 * cs - v1 * sn) * scale;
                    o1 = (v0 * sn + v1 * cs) * scale;
                    d = 128 + pd;
                }
                size_t base = ((size_t)(b*NH + h) * SS + s) * 384;
                __half h0 = __float2half(o0), h1 = __float2half(o1);
                float  l0f = o0 - __half2float(h0), l1f = o1 - __half2float(h1);
                *(uint32_t*)&Q[base + d]       = (uint32_t)(*(uint16_t*)&h0) | ((uint32_t)(*(uint16_t*)&h1) << 16);
                *(uint32_t*)&Q[base + 192 + d] = pack2h(l0f, l1f);
            }
        }
}

// ---------------- RMSNorm -> fp16 hi-only ----------------
__global__ void rmsnorm_h_k(const float* __restrict__ x, const float* __restrict__ w,
                            __half* __restrict__ out, int W, int pitch)
{
    const int row = blockIdx.x;
    const float* xr = x + (size_t)row * pitch;
    const float4* x4 = (const float4*)xr;
    float ss = 0.f;
    int W4 = W >> 2;
    for (int i = threadIdx.x; i < W4; i += blockDim.x) {
        float4 v = x4[i];
        ss += v.x*v.x + v.y*v.y + v.z*v.z + v.w*v.w;
    }
    __shared__ float red[32];
#pragma unroll
    for (int o = 16; o; o >>= 1) ss += __shfl_down_sync(0xffffffffu, ss, o);
    if ((threadIdx.x & 31) == 0) red[threadIdx.x >> 5] = ss;
    __syncthreads();
    if (threadIdx.x < 32) {
        float v = (threadIdx.x < (blockDim.x >> 5)) ? red[threadIdx.x] : 0.f;
#pragma unroll
        for (int o = 16; o; o >>= 1) v += __shfl_down_sync(0xffffffffu, v, o);
        if (threadIdx.x == 0) red[0] = rsqrtf(v / (float)W + 1e-6f);
    }
    __syncthreads();
    float r = red[0];
    __half* orow = out + (size_t)row * W;
    const float4* w4 = (const float4*)w;
    int W8 = W >> 3;
    for (int i8 = threadIdx.x; i8 < W8; i8 += blockDim.x) {
        float4 a = x4[i8*2], b = x4[i8*2+1];
        float4 wa = w4[i8*2], wb = w4[i8*2+1];
        __align__(16) __half h[8];
        h[0]=__float2half(a.x*r*wa.x); h[1]=__float2half(a.y*r*wa.y);
        h[2]=__float2half(a.z*r*wa.z); h[3]=__float2half(a.w*r*wa.w);
        h[4]=__float2half(b.x*r*wb.x); h[5]=__float2half(b.y*r*wb.y);
        h[6]=__float2half(b.z*r*wb.z); h[7]=__float2half(b.w*r*wb.w);
        *(uint4*)&orow[i8*8] = *(uint4*)h;
    }
}

// ---------------- RoPE on k_rope slice of dall ----------------
__global__ void rope_k(float* __restrict__ x, int pitch, int colOff,
                       int nheads, int d, int total_pairs)
{
    int idx = blockIdx.x * blockDim.x + threadIdx.x;
    if (idx >= total_pairs) return;
    int pairs_per_row = nheads * (d / 2);
    int row = idx / pairs_per_row;
    int p   = idx % pairs_per_row;
    int h = p / (d / 2);
    int i = p % (d / 2);
    int pos = row % SS;
    float inv = powf(10000.f, (-2.0f * (float)i) / (float)d);
    float ang = (float)pos * inv;
    float s, c;
    sincosf(ang, &s, &c);
    float* base = x + (size_t)row * pitch + colOff + h * d + 2 * i;
    float x1 = base[0], x2 = base[1];
    base[0] = x1 * c - x2 * s;
    base[1] = x1 * s + x2 * c;
}

// ---------------- pack K rope region only (d in [128,192)) ----------------
__global__ void pack_k_rope(const float* __restrict__ dall, __half* __restrict__ out)
{
    long long idx = (long long)blockIdx.x * blockDim.x + threadIdx.x;
    if (idx >= (long long)BB*NH*SS*8) return;
    int c8 = (int)(idx % 8);
    int s  = (int)((idx / 8) % SS);
    int bh = (int)(idx / (8LL*SS));
    int b = bh / NH;
    size_t m = (size_t)b * SS + s;
    int off = c8 * 8;
    const float* src = &dall[m * NDOWN + 2048 + off];
    float4 a = ((const float4*)src)[0], bb = ((const float4*)src)[1];
    __align__(16) __half hh[8];
    hh[0]=__float2half(a.x);  hh[1]=__float2half(a.y);  hh[2]=__float2half(a.z);  hh[3]=__float2half(a.w);
    hh[4]=__float2half(bb.x); hh[5]=__float2half(bb.y); hh[6]=__float2half(bb.z); hh[7]=__float2half(bb.w);
    *(uint4*)&out[((size_t)bh * SS + s) * 192 + 128 + off] = *(uint4*)hh;
}

// ---------------- pack V transpose ----------------
__global__ __launch_bounds__(256) void pack_v(const __half* __restrict__ kv16,
                                              __half* __restrict__ vt)
{
    __shared__ float vs[64][129];
    const int t = blockIdx.x, h = blockIdx.y, b = blockIdx.z;
    const int bh = b*NH + h;
    const int tid = threadIdx.x;
    for (int i = tid; i < 64*16; i += 256) {
        int r = i >> 4, d8 = (i & 15) * 8;
        size_t m = (size_t)b * SS + t*64 + r;
        uint4 raw = *(const uint4*)&kv16[m * (NH*256) + h*256 + 128 + d8];
        const __half* hp = (const __half*)&raw;
#pragma unroll
        for (int k = 0; k < 8; k++) vs[r][d8 + k] = __half2float(hp[k]);
    }
    __syncthreads();
    for (int i = tid; i < 128*8; i += 256) {
        int d = i >> 3, w8 = i & 7;
        int kk0 = w8 * 8;
        __align__(16) __half p[8];
#pragma unroll
        for (int k = 0; k < 8; k++) p[k] = __float2half(vs[kk0 + k][d]);
        *(uint4*)&vt[((size_t)bh * 128 + d) * SS + t*64 + kk0] = *(uint4*)p;
    }
}

// ============================================================
// HMMA flash attention — Q resident; P hi-only (single PV term)
// ============================================================
#define KBASE 49152u
#define VBASE 73728u
#define PBASE 90112u
#define ATT_SMEM 108544

__global__ __launch_bounds__(256, 2) void attn_mma(
    const __half* __restrict__ Qsp, const __half* __restrict__ Ksp,
    const __half* __restrict__ Vt, __half* __restrict__ ats)
{
    extern __shared__ __align__(16) char smem[];
    const uint32_t sb = smem_u32(smem);
    const int qt = (int)gridDim.x - 1 - (int)blockIdx.x;
    const int h = blockIdx.y, b = blockIdx.z;
    const int bh = b*NH + h;
    const int q0 = qt * 64;
    const int tid = threadIdx.x, lane = tid & 31;
    const int wm = (tid >> 5) & 3, wn = tid >> 7;

    const __half* Qg = Qsp + ((size_t)bh * SS + q0) * 384;
    const __half* Kg = Ksp + (size_t)bh * SS * 192;
    const __half* Vg = Vt  + (size_t)bh * 128 * SS;

    float* redmax = (float*)(smem + 107520);
    float* redsum = (float*)(smem + 108032);

    {
        int r = tid >> 3, ch = tid & 7;
#pragma unroll
        for (int cq = 0; cq < 6; cq++) {
#pragma unroll
            for (int it = 0; it < 2; it++) {
                int rr = r + it*32;
                CPA16(sb + (uint32_t)cq*8192u + sw128(rr, ch),
                      Qg + (size_t)rr*384 + cq*64 + ch*8);
            }
        }
        CPCOMMIT();
    }

    float acc_o[8][4];
#pragma unroll
    for (int i = 0; i < 8; i++)
#pragma unroll
        for (int j = 0; j < 4; j++) acc_o[i][j] = 0.f;
    float m0 = -1e30f, m1 = -1e30f, l0 = 0.f, l1 = 0.f;

    const int a_row  = lane & 15;
    const int a_ch   = lane >> 4;
    const int b_nrow = (lane & 7) + ((lane & 16) ? 8 : 0);
    const int b_ch   = (lane >> 3) & 1;
    const int r0 = wm*16 + (lane >> 2);

    for (int t = 0; t <= qt; t++) {
        const int k0 = t * 64;
        {
            int r = tid >> 3, ch = tid & 7;
#pragma unroll
            for (int slot = 0; slot < 2; slot++) {
#pragma unroll
                for (int it = 0; it < 2; it++) {
                    int rr = r + it*32;
                    CPA16(sb + KBASE + (uint32_t)slot*8192u + sw128(rr, ch),
                          Kg + (size_t)(k0 + rr)*192 + slot*64 + ch*8);
                }
                CPCOMMIT();
            }
#pragma unroll
            for (int it = 0; it < 4; it++) {
                int i = tid + it*256;
                int d = i >> 3, vch = i & 7;
                CPA16(sb + VBASE + sw128(d, vch), Vg + (size_t)d*SS + t*64 + vch*8);
            }
            CPCOMMIT();
        }

        float acc_s[4][4];
#pragma unroll
        for (int i = 0; i < 4; i++)
#pragma unroll
            for (int j = 0; j < 4; j++) acc_s[i][j] = 0.f;

#pragma unroll
        for (int c = 0; c < 3; c++) {
            if (c < 2) { CPWAIT(2); } else { CPWAIT(0); }
            __syncthreads();
            if (c == 0) {
                int r = tid >> 3, ch = tid & 7;
#pragma unroll
                for (int it = 0; it < 2; it++) {
                    int rr = r + it*32;
                    CPA16(sb + KBASE + 2u*8192u + sw128(rr, ch),
                          Kg + (size_t)(k0 + rr)*192 + 2*64 + ch*8);
                }
                CPCOMMIT();
            }
            uint32_t kb = sb + KBASE + (uint32_t)c*8192u;
            uint32_t qh = sb + (uint32_t)c*8192u;
            uint32_t ql = sb + (uint32_t)(c+3)*8192u;
#pragma unroll
            for (int ks = 0; ks < 4; ks++) {
                uint32_t a0[4], a1[4];
                ldsm4(a0, qh + sw128(wm*16 + a_row, ks*2 + a_ch));
                ldsm4(a1, ql + sw128(wm*16 + a_row, ks*2 + a_ch));
#pragma unroll
                for (int g = 0; g < 2; g++) {
                    uint32_t bb[4];
                    ldsm4(bb, kb + sw128(wn*32 + g*16 + b_nrow, ks*2 + b_ch));
                    mma16816(acc_s[g*2],   a0, bb[0], bb[1]);
                    mma16816(acc_s[g*2+1], a0, bb[2], bb[3]);
                    mma16816(acc_s[g*2],   a1, bb[0], bb[1]);
                    mma16816(acc_s[g*2+1], a1, bb[2], bb[3]);
                }
            }
        }

        if (t == qt) {
#pragma unroll
            for (int nt = 0; nt < 4; nt++) {
                int colb = wn*32 + nt*8 + (lane & 3)*2;
                if (colb     > r0)     acc_s[nt][0] = -1e30f;
                if (colb + 1 > r0)     acc_s[nt][1] = -1e30f;
                if (colb     > r0 + 8) acc_s[nt][2] = -1e30f;
                if (colb + 1 > r0 + 8) acc_s[nt][3] = -1e30f;
            }
        }

        float mx0 = -1e30f, mx1 = -1e30f;
#pragma unroll
        for (int nt = 0; nt < 4; nt++) {
            mx0 = fmaxf(mx0, fmaxf(acc_s[nt][0], acc_s[nt][1]));
            mx1 = fmaxf(mx1, fmaxf(acc_s[nt][2], acc_s[nt][3]));
        }
        mx0 = fmaxf(mx0, __shfl_xor_sync(0xffffffffu, mx0, 1));
        mx0 = fmaxf(mx0, __shfl_xor_sync(0xffffffffu, mx0, 2));
        mx1 = fmaxf(mx1, __shfl_xor_sync(0xffffffffu, mx1, 1));
        mx1 = fmaxf(mx1, __shfl_xor_sync(0xffffffffu, mx1, 2));
        if ((lane & 3) == 0) {
            redmax[wn*64 + r0]     = mx0;
            redmax[wn*64 + r0 + 8] = mx1;
        }
        __syncthreads();
        float tm0 = fmaxf(mx0, redmax[(wn^1)*64 + r0]);
        float tm1 = fmaxf(mx1, redmax[(wn^1)*64 + r0 + 8]);
        float nm0 = fmaxf(m0, tm0), nm1 = fmaxf(m1, tm1);
        float f0 = __expf(m0 - nm0), f1 = __expf(m1 - nm1);

        float s0 = 0.f, s1 = 0.f;
#pragma unroll
        for (int nt = 0; nt < 4; nt++) {
            acc_s[nt][0] = __expf(acc_s[nt][0] - nm0);
            acc_s[nt][1] = __expf(acc_s[nt][1] - nm0);
            acc_s[nt][2] = __expf(acc_s[nt][2] - nm1);
            acc_s[nt][3] = __expf(acc_s[nt][3] - nm1);
            s0 += acc_s[nt][0] + acc_s[nt][1];
            s1 += acc_s[nt][2] + acc_s[nt][3];
        }
        s0 += __shfl_xor_sync(0xffffffffu, s0, 1);
        s0 += __shfl_xor_sync(0xffffffffu, s0, 2);
        s1 += __shfl_xor_sync(0xffffffffu, s1, 1);
        s1 += __shfl_xor_sync(0xffffffffu, s1, 2);
        if ((lane & 3) == 0) {
            redsum[wn*64 + r0]     = s0;
            redsum[wn*64 + r0 + 8] = s1;
        }
        // P hi-only to smem
        {
            char* P = smem + PBASE;
            int colb = wn*32 + (lane & 3)*2;
#pragma unroll
            for (int nt = 0; nt < 4; nt++) {
                int col = colb + nt*8;
#pragma unroll
                for (int half = 0; half < 2; half++) {
                    int row = r0 + half*8;
                    *(uint32_t*)(P + row*272 + col*2) =
                        pack2h(acc_s[nt][half*2], acc_s[nt][half*2+1]);
                }
            }
        }
        __syncthreads();
        float ts0 = s0 + redsum[(wn^1)*64 + r0];
        float ts1 = s1 + redsum[(wn^1)*64 + r0 + 8];
        l0 = l0 * f0 + ts0;
        l1 = l1 * f1 + ts1;
        m0 = nm0; m1 = nm1;
#pragma unroll
        for (int nt = 0; nt < 8; nt++) {
            acc_o[nt][0] *= f0; acc_o[nt][1] *= f0;
            acc_o[nt][2] *= f1; acc_o[nt][3] *= f1;
        }

        // PV: single (Ph, Vh) pass
#pragma unroll
        for (int ks = 0; ks < 4; ks++) {
            uint32_t a[4];
            ldsm4(a, sb + PBASE + (uint32_t)((wm*16 + a_row)*272)
                     + (uint32_t)(ks*32 + a_ch*16));
#pragma unroll
            for (int g = 0; g < 4; g++) {
                uint32_t bb[4];
                ldsm4(bb, sb + VBASE + sw128(wn*64 + g*16 + b_nrow, ks*2 + b_ch));
                mma16816(acc_o[g*2],   a, bb[0], bb[1]);
                mma16816(acc_o[g*2+1], a, bb[2], bb[3]);
            }
        }
        __syncthreads();
    }

    float il0 = 1.f / l0, il1 = 1.f / l1;
    size_t mrow0 = (size_t)b * SS + q0 + r0;
#pragma unroll
    for (int nt = 0; nt < 8; nt++) {
        int col = h*128 + wn*64 + nt*8 + (lane & 3)*2;
#pragma unroll
        for (int half = 0; half < 2; half++) {
            float oa = acc_o[nt][half*2]   * (half ? il1 : il0);
            float ob = acc_o[nt][half*2+1] * (half ? il1 : il0);
            size_t row = mrow0 + half*8;
            ((uint32_t*)(ats + row * 2048))[col >> 1] = pack2h(oa, ob);
        }
    }
}

// ---------------- host orchestration ----------------
static void convB(const float* in, __half* out, int R, int Rpad, int C, int inPitch)
{
    long long tot = (long long)Rpad * (C >> 3);
    cvtB_k<<<(int)((tot + 255) / 256), 256>>>(in, out, R, Rpad, C, inPitch);
}

extern "C" void kernel_launch(void* const* d_in, const int* in_sizes, int n_in,
                              void* d_out, int out_size)
{
    const float* x        = (const float*)d_in[0];
    const float* wq_down  = (const float*)d_in[1];
    const float* q_norm_w = (const float*)d_in[2];
    const float* wq_up    = (const float*)d_in[3];
    const float* wq_rope  = (const float*)d_in[4];
    const float* wkv_down = (const float*)d_in[5];
    const float* kv_norm_w= (const float*)d_in[6];
    const float* wkv_up   = (const float*)d_in[7];
    const float* wk_rope  = (const float*)d_in[8];
    const float* wo       = (const float*)d_in[9];
    float* out = (float*)d_out;

    float* dall;
    cudaGetSymbolAddress((void**)&dall, g_dall);

    __half *xs, *wdall, *qcs, *wuall, *kvcs, *wkvu, *kvu16, *ats, *wos, *qsp, *ksp, *vt;
    cudaGetSymbolAddress((void**)&xs,    g_xs);
    cudaGetSymbolAddress((void**)&wdall, g_wdall);
    cudaGetSymbolAddress((void**)&qcs,   g_qcs);
    cudaGetSymbolAddress((void**)&wuall, g_wuall);
    cudaGetSymbolAddress((void**)&kvcs,  g_kvcs);
    cudaGetSymbolAddress((void**)&wkvu,  g_wkvu);
    cudaGetSymbolAddress((void**)&kvu16, g_kvu16);
    cudaGetSymbolAddress((void**)&ats,   g_ats);
    cudaGetSymbolAddress((void**)&wos,   g_wos);
    cudaGetSymbolAddress((void**)&qsp,   g_qsp);
    cudaGetSymbolAddress((void**)&ksp,   g_ksp);
    cudaGetSymbolAddress((void**)&vt,    g_vt);

    cudaFuncSetAttribute(gemm_f32,    cudaFuncAttributeMaxDynamicSharedMemorySize, GEMM_SMEM);
    cudaFuncSetAttribute(gemm_kvpack, cudaFuncAttributeMaxDynamicSharedMemorySize, GEMM_SMEM);
    cudaFuncSetAttribute(gemm_qpack,  cudaFuncAttributeMaxDynamicSharedMemorySize, GEMM_SMEM);

    // ---- stage 1: merged down projection ----
    convB(x, xs, MT, MT, DIMM, DIMM);
    {
        long long tot = (long long)NDOWNP * (DIMM >> 3);
        cvtW_down_k<<<(int)((tot + 255) / 256), 256>>>(wq_down, wkv_down, wk_rope, wdall);
    }
    gemm_f32<<<dim3((NDOWN + 127)/128, MT/128), 256, GEMM_SMEM>>>(xs, wdall, dall, MT, NDOWN, DIMM);

    // ---- rmsnorm -> fp16 hi; kr rope ----
    rmsnorm_h_k<<<MT, 256>>>(dall,      q_norm_w,  qcs,  QR,  NDOWN);
    rmsnorm_h_k<<<MT, 256>>>(dall + QR, kv_norm_w, kvcs, KVR, NDOWN);
    rope_k<<<(MT*32 + 255)/256, 256>>>(dall, NDOWN, QR+KVR, 1, DR, MT*32);

    // ---- stage 2: up projections (fused packing epilogues) ----
    {
        long long tot = (long long)NUP * (QR >> 3);
        cvtW_up_k<<<(int)((tot + 255) / 256), 256>>>(wq_up, wq_rope, wuall);
    }
    gemm_qpack<<<dim3(NUP/128, MT/128), 256, GEMM_SMEM>>>(qcs, wuall, qsp, MT, NUP, QR);
    convB(wkv_up, wkvu, NH*(DN+DVV), NH*(DN+DVV), KVR, KVR);
    gemm_kvpack<<<dim3((NH*(DN+DVV))/128, MT/128), 256, GEMM_SMEM>>>(kvcs, wkvu, kvu16, ksp, MT, NH*(DN+DVV), KVR);

    // ---- remaining packs ----
    {
        long long tot = (long long)BB*NH*SS*8;
        pack_k_rope<<<(int)((tot + 255) / 256), 256>>>(dall, ksp);
    }
    pack_v<<<dim3(SS/64, NH, BB), 256>>>(kvu16, vt);

    // ---- HMMA flash attention ----
    cudaFuncSetAttribute(attn_mma, cudaFuncAttributeMaxDynamicSharedMemorySize, ATT_SMEM);
    attn_mma<<<dim3(SS/64, NH, BB), 256, ATT_SMEM>>>(qsp, ksp, vt, ats);

    // ---- output projection ----
    convB(wo, wos, DIMM, DIMM, NH*DVV, NH*DVV);
    gemm_f32<<<dim3((DIMM + 127)/128, MT/128), 256, GEMM_SMEM>>>(ats, wos, out, MT, DIMM, NH*DVV);
}

// round 16
// speedup vs baseline: 1.5471x; 1.0590x over previous
#include <cuda_runtime.h>
#include <cuda_fp16.h>
#include <math.h>
#include <stdint.h>

#define BB 2
#define SS 2048
#define DIMM 2048
#define NH 16
#define QR 1536
#define KVR 512
#define DN 128
#define DR 64
#define DVV 128
#define MT (BB*SS)

#define NDOWN 2112
#define NDOWNP 2176
#define NUP 3072

// ---------------- fp32 scratch ----------------
__device__ float g_dall[MT*NDOWN];

// ---------------- fp16 scratch ----------------
__device__ __half g_xs   [MT    * DIMM];
__device__ __half g_wdall[NDOWNP* DIMM];
__device__ __half g_qcs  [MT    * QR];
__device__ __half g_wuall[NUP   * QR];
__device__ __half g_kvcs [MT    * KVR];
__device__ __half g_wkvu [(NH*(DN+DVV)) * KVR];
__device__ __half g_kvu16[MT    * (NH*(DN+DVV))];   // only V half valid
__device__ __half g_ats  [MT    * (NH*DVV)];
__device__ __half g_wos  [DIMM  * (NH*DVV)];

// ---------------- attention packed operands ----------------
__device__ __half g_qsp[BB*NH*SS*384];
__device__ __half g_ksp[BB*NH*SS*192];
__device__ __half g_vt [BB*NH*128*SS];

// ============================================================
// helpers
// ============================================================
__device__ __forceinline__ uint32_t smem_u32(const void* p){
    uint32_t a;
    asm("{ .reg .u64 t; cvta.to.shared.u64 t, %1; cvt.u32.u64 %0, t; }" : "=r"(a) : "l"(p));
    return a;
}
#define CPA16(dst, src) asm volatile("cp.async.cg.shared.global [%0], [%1], 16;" :: "r"(dst), "l"(src))
#define CPCOMMIT()      asm volatile("cp.async.commit_group;")
#define CPWAIT(n)       asm volatile("cp.async.wait_group %0;" :: "n"(n))

__device__ __forceinline__ void ldsm4(uint32_t* r, uint32_t addr){
    asm volatile("ldmatrix.sync.aligned.m8n8.x4.shared.b16 {%0,%1,%2,%3}, [%4];"
        : "=r"(r[0]), "=r"(r[1]), "=r"(r[2]), "=r"(r[3]) : "r"(addr));
}
__device__ __forceinline__ void mma16816(float* c, const uint32_t* a, uint32_t b0, uint32_t b1){
    asm volatile("mma.sync.aligned.m16n8k16.row.col.f32.f16.f16.f32 "
        "{%0,%1,%2,%3}, {%4,%5,%6,%7}, {%8,%9}, {%0,%1,%2,%3};"
        : "+f"(c[0]), "+f"(c[1]), "+f"(c[2]), "+f"(c[3])
        : "r"(a[0]), "r"(a[1]), "r"(a[2]), "r"(a[3]), "r"(b0), "r"(b1));
}
__device__ __forceinline__ uint32_t sw128(int row, int chunk){
    return (uint32_t)(row * 128 + ((chunk ^ (row & 7)) * 16));
}
__device__ __forceinline__ uint32_t pack2h(float a, float b){
    __half ha = __float2half(a), hb = __float2half(b);
    return (uint32_t)(*(uint16_t*)&ha) | ((uint32_t)(*(uint16_t*)&hb) << 16);
}
// convert 8 contiguous fp32 -> fp16, write 16B
__device__ __forceinline__ void cvt8(const float* src, __half* dst){
    float4 a = ((const float4*)src)[0], b = ((const float4*)src)[1];
    __align__(16) __half h[8];
    h[0]=__float2half(a.x); h[1]=__float2half(a.y); h[2]=__float2half(a.z); h[3]=__float2half(a.w);
    h[4]=__float2half(b.x); h[5]=__float2half(b.y); h[6]=__float2half(b.z); h[7]=__float2half(b.w);
    *(uint4*)dst = *(uint4*)h;
}
__device__ __forceinline__ void zero8(__half* dst){
    uint4 z = make_uint4(0,0,0,0);
    *(uint4*)dst = z;
}

// ============================================================
// single mega conversion kernel: xs | wdall | wuall | wkvu | wos
// ============================================================
#define CVT_N0 ((long long)MT * (DIMM>>3))                  // xs
#define CVT_N1 (CVT_N0 + (long long)NDOWNP * (DIMM>>3))     // wdall
#define CVT_N2 (CVT_N1 + (long long)NUP * (QR>>3))          // wuall
#define CVT_N3 (CVT_N2 + (long long)(NH*256) * (KVR>>3))    // wkvu
#define CVT_N4 (CVT_N3 + (long long)DIMM * ((NH*DVV)>>3))   // wos

__global__ void cvt_all(const float* __restrict__ x,
                        const float* __restrict__ wqd, const float* __restrict__ wkvd,
                        const float* __restrict__ wkr,
                        const float* __restrict__ wqu, const float* __restrict__ wqr,
                        const float* __restrict__ wkvup, const float* __restrict__ wo,
                        __half* __restrict__ xs, __half* __restrict__ wdall,
                        __half* __restrict__ wuall, __half* __restrict__ wkvu,
                        __half* __restrict__ wos)
{
    long long i = (long long)blockIdx.x * blockDim.x + threadIdx.x;
    if (i >= CVT_N4) return;
    if (i < CVT_N0) {
        int r = (int)(i >> 8), c = ((int)i & 255) << 3;
        cvt8(x + (size_t)r * DIMM + c, xs + (size_t)r * DIMM + c);
    } else if (i < CVT_N1) {
        long long j = i - CVT_N0;
        int r = (int)(j >> 8), c = ((int)j & 255) << 3;
        __half* dst = wdall + (size_t)r * DIMM + c;
        if (r < QR)          cvt8(wqd  + (size_t)r * DIMM + c, dst);
        else if (r < QR+KVR) cvt8(wkvd + (size_t)(r-QR) * DIMM + c, dst);
        else if (r < NDOWN)  cvt8(wkr  + (size_t)(r-QR-KVR) * DIMM + c, dst);
        else                 zero8(dst);
    } else if (i < CVT_N2) {
        long long j = i - CVT_N1;
        int r = (int)(j / 192), c = ((int)(j % 192)) << 3;
        const float* src = (r < NH*DN) ? wqu + (size_t)r * QR + c
                                       : wqr + (size_t)(r - NH*DN) * QR + c;
        cvt8(src, wuall + (size_t)r * QR + c);
    } else if (i < CVT_N3) {
        long long j = i - CVT_N2;
        int r = (int)(j >> 6), c = ((int)j & 63) << 3;
        cvt8(wkvup + (size_t)r * KVR + c, wkvu + (size_t)r * KVR + c);
    } else {
        long long j = i - CVT_N3;
        int r = (int)(j >> 8), c = ((int)j & 255) << 3;
        cvt8(wo + (size_t)r * (NH*DVV) + c, wos + (size_t)r * (NH*DVV) + c);
    }
}

// ============================================================
// GEMM mainloop macro — requires m0, n0, A, B, K defined in scope
// ============================================================
#define STAGES 3
#define STAGE_BYTES 32768
#define GEMM_SMEM (STAGES*STAGE_BYTES)

#define GEMM_MAINLOOP(ACC)                                                      \
    extern __shared__ __align__(16) char smem[];                                \
    const uint32_t sb = smem_u32(smem);                                         \
    const int tid = threadIdx.x, lane = tid & 31;                               \
    const int wm = (tid >> 5) & 3;                                              \
    const int wn = tid >> 7;                                                    \
    float ACC[2][8][4];                                                         \
    _Pragma("unroll")                                                           \
    for (int i = 0; i < 2; i++)                                                 \
        _Pragma("unroll")                                                       \
        for (int j = 0; j < 8; j++)                                             \
            _Pragma("unroll")                                                   \
            for (int q = 0; q < 4; q++) ACC[i][j][q] = 0.f;                     \
    const int KT = K >> 6;                                                      \
    const __half* Ag0 = A + (size_t)m0 * K;                                     \
    const __half* Bg0 = B + (size_t)n0 * K;                                     \
    const int fr = tid >> 3;                                                    \
    const int fc = tid & 7;                                                     \
    auto fill = [&](int j){                                                     \
        uint32_t base = sb + (uint32_t)(j % STAGES) * STAGE_BYTES;              \
        int k0 = j << 6;                                                        \
        _Pragma("unroll")                                                       \
        for (int i = 0; i < 4; i++) {                                           \
            int r = fr + i * 32;                                                \
            CPA16(base + sw128(r, fc), Ag0 + (size_t)r * K + k0 + fc*8);        \
        }                                                                       \
        _Pragma("unroll")                                                       \
        for (int i = 0; i < 4; i++) {                                           \
            int r = fr + i * 32;                                                \
            CPA16(base + 16384u + sw128(r, fc), Bg0 + (size_t)r * K + k0 + fc*8);\
        }                                                                       \
        CPCOMMIT();                                                             \
    };                                                                          \
    fill(0);                                                                    \
    fill(1);                                                                    \
    const int a_row  = lane & 15;                                               \
    const int a_ch   = lane >> 4;                                               \
    const int b_nrow = (lane & 7) + ((lane & 16) ? 8 : 0);                      \
    const int b_ch   = (lane >> 3) & 1;                                         \
    for (int kt = 0; kt < KT; kt++) {                                           \
        CPWAIT(1);                                                              \
        __syncthreads();                                                        \
        if (kt + 2 < KT) fill(kt + 2);                                          \
        else CPCOMMIT();                                                        \
        uint32_t aT = sb + (uint32_t)(kt % STAGES) * STAGE_BYTES;               \
        uint32_t bT = aT + 16384u;                                              \
        _Pragma("unroll")                                                       \
        for (int ks = 0; ks < 4; ks++) {                                        \
            uint32_t a[2][4];                                                   \
            _Pragma("unroll")                                                   \
            for (int i = 0; i < 2; i++)                                         \
                ldsm4(a[i], aT + sw128(wm*32 + i*16 + a_row, ks*2 + a_ch));     \
            uint32_t b[4][4];                                                   \
            _Pragma("unroll")                                                   \
            for (int g = 0; g < 4; g++)                                         \
                ldsm4(b[g], bT + sw128(wn*64 + g*16 + b_nrow, ks*2 + b_ch));    \
            _Pragma("unroll")                                                   \
            for (int i = 0; i < 2; i++)                                         \
                _Pragma("unroll")                                               \
                for (int g = 0; g < 4; g++) {                                   \
                    mma16816(ACC[i][2*g],   a[i], b[g][0], b[g][1]);            \
                    mma16816(ACC[i][2*g+1], a[i], b[g][2], b[g][3]);            \
                }                                                               \
        }                                                                       \
    }

// ---- fp32-out GEMM ----
__global__ __launch_bounds__(256, 2) void gemm_f32(
    const __half* __restrict__ A, const __half* __restrict__ B,
    float* __restrict__ C, int M, int N, int K)
{
    const int m0 = blockIdx.y * 128, n0 = blockIdx.x * 128;
    GEMM_MAINLOOP(acc)
    const int rb = m0 + wm*32;
    const int cb = n0 + wn*64;
#pragma unroll
    for (int i = 0; i < 2; i++)
#pragma unroll
        for (int j = 0; j < 8; j++) {
            int c = cb + j*8 + (lane & 3)*2;
            if (c < N) {
                int r = rb + i*16 + (lane >> 2);
                *(float2*)&C[(size_t)r * N + c]     = make_float2(acc[i][j][0], acc[i][j][1]);
                *(float2*)&C[(size_t)(r+8) * N + c] = make_float2(acc[i][j][2], acc[i][j][3]);
            }
        }
}

// ---- merged up-proj GEMM: qpack (bid<768) + kvpack ----
#define QP_BLOCKS ((MT/128)*(NUP/128))          // 32*24 = 768
#define KV_BLOCKS ((MT/128)*((NH*256)/128))     // 32*32 = 1024

__global__ __launch_bounds__(256, 2) void gemm_qkv(
    const __half* __restrict__ qcs, const __half* __restrict__ wuall,
    const __half* __restrict__ kvcs, const __half* __restrict__ wkvu,
    __half* __restrict__ Q, __half* __restrict__ kvu16, __half* __restrict__ ksp)
{
    int bid = blockIdx.x;
    const __half *A, *B;
    int K, m0, n0, mode;
    if (bid < QP_BLOCKS) {
        mode = 0; A = qcs; B = wuall; K = QR;
        m0 = (bid / (NUP/128)) * 128;
        n0 = (bid % (NUP/128)) * 128;
    } else {
        bid -= QP_BLOCKS;
        mode = 1; A = kvcs; B = wkvu; K = KVR;
        m0 = (bid / ((NH*256)/128)) * 128;
        n0 = (bid % ((NH*256)/128)) * 128;
    }
    GEMM_MAINLOOP(acc)
    const int rb = m0 + wm*32;
    const int cb = n0 + wn*64;
    if (mode == 0) {
        const float scale = 0.072168783648703220563f;   // 1/sqrt(192)
#pragma unroll
        for (int i = 0; i < 2; i++)
#pragma unroll
            for (int j = 0; j < 8; j++) {
                int c = cb + j*8 + (lane & 3)*2;
#pragma unroll
                for (int half = 0; half < 2; half++) {
                    int r = rb + i*16 + (lane >> 2) + half*8;
                    float v0 = acc[i][j][half*2], v1 = acc[i][j][half*2+1];
                    int b = r >> 11;
                    int s = r & (SS-1);
                    int h, d;
                    float o0, o1;
                    if (c < 2048) {
                        h = c >> 7; d = c & 127;
                        o0 = v0 * scale; o1 = v1 * scale;
                    } else {
                        int cc = c - 2048;
                        h = cc >> 6;
                        int pd = cc & 63;
                        int p = pd >> 1;
                        float inv = powf(10000.f, (-2.0f * (float)p) / 64.f);
                        float sn, cs;
                        sincosf((float)s * inv, &sn, &cs);
                        o0 = (v0 * cs - v1 * sn) * scale;
                        o1 = (v0 * sn + v1 * cs) * scale;
                        d = 128 + pd;
                    }
                    size_t base = ((size_t)(b*NH + h) * SS + s) * 384;
                    __half h0 = __float2half(o0), h1 = __float2half(o1);
                    float  l0f = o0 - __half2float(h0), l1f = o1 - __half2float(h1);
                    *(uint32_t*)&Q[base + d]       = (uint32_t)(*(uint16_t*)&h0) | ((uint32_t)(*(uint16_t*)&h1) << 16);
                    *(uint32_t*)&Q[base + 192 + d] = pack2h(l0f, l1f);
                }
            }
    } else {
#pragma unroll
        for (int i = 0; i < 2; i++)
#pragma unroll
            for (int j = 0; j < 8; j++) {
                int c = cb + j*8 + (lane & 3)*2;
                int h = c >> 8, d = c & 255;
#pragma unroll
                for (int half = 0; half < 2; half++) {
                    int r = rb + i*16 + (lane >> 2) + half*8;
                    uint32_t val = pack2h(acc[i][j][half*2], acc[i][j][half*2+1]);
                    if (d < 128) {
                        int b = r >> 11, s = r & (SS-1);
                        *(uint32_t*)&ksp[((size_t)(b*NH + h) * SS + s) * 192 + d] = val;
                    } else {
                        *(uint32_t*)&kvu16[(size_t)r * (NH*256) + c] = val;
                    }
                }
            }
    }
}

// ---------------- merged RMSNorm -> fp16 hi (grid.y: 0=q, 1=kv) ----------------
__global__ void rmsnorm2_k(const float* __restrict__ dall,
                           const float* __restrict__ qw, const float* __restrict__ kvw,
                           __half* __restrict__ qcs, __half* __restrict__ kvcs)
{
    const int which = blockIdx.y;
    const int row = blockIdx.x;
    const int W = which ? KVR : QR;
    const float* xr = dall + (size_t)row * NDOWN + (which ? QR : 0);
    const float* w  = which ? kvw : qw;
    __half* orow = (which ? kvcs + (size_t)row * KVR : qcs + (size_t)row * QR);

    const float4* x4 = (const float4*)xr;
    float ss = 0.f;
    int W4 = W >> 2;
    for (int i = threadIdx.x; i < W4; i += blockDim.x) {
        float4 v = x4[i];
        ss += v.x*v.x + v.y*v.y + v.z*v.z + v.w*v.w;
    }
    __shared__ float red[32];
#pragma unroll
    for (int o = 16; o; o >>= 1) ss += __shfl_down_sync(0xffffffffu, ss, o);
    if ((threadIdx.x & 31) == 0) red[threadIdx.x >> 5] = ss;
    __syncthreads();
    if (threadIdx.x < 32) {
        float v = (threadIdx.x < (blockDim.x >> 5)) ? red[threadIdx.x] : 0.f;
#pragma unroll
        for (int o = 16; o; o >>= 1) v += __shfl_down_sync(0xffffffffu, v, o);
        if (threadIdx.x == 0) red[0] = rsqrtf(v / (float)W + 1e-6f);
    }
    __syncthreads();
    float r = red[0];
    const float4* w4 = (const float4*)w;
    int W8 = W >> 3;
    for (int i8 = threadIdx.x; i8 < W8; i8 += blockDim.x) {
        float4 a = x4[i8*2], b = x4[i8*2+1];
        float4 wa = w4[i8*2], wb = w4[i8*2+1];
        __align__(16) __half h[8];
        h[0]=__float2half(a.x*r*wa.x); h[1]=__float2half(a.y*r*wa.y);
        h[2]=__float2half(a.z*r*wa.z); h[3]=__float2half(a.w*r*wa.w);
        h[4]=__float2half(b.x*r*wb.x); h[5]=__float2half(b.y*r*wb.y);
        h[6]=__float2half(b.z*r*wb.z); h[7]=__float2half(b.w*r*wb.w);
        *(uint4*)&orow[i8*8] = *(uint4*)h;
    }
}

// ---------------- fused kr RoPE + pack into ksp ----------------
__global__ void rope_pack_kr(const float* __restrict__ dall, __half* __restrict__ out)
{
    long long idx = (long long)blockIdx.x * blockDim.x + threadIdx.x;
    if (idx >= (long long)BB*NH*SS*8) return;
    int c8 = (int)(idx % 8);
    int s  = (int)((idx / 8) % SS);
    int bh = (int)(idx / (8LL*SS));
    int b = bh / NH;
    size_t m = (size_t)b * SS + s;
    int off = c8 * 8;
    const float* src = &dall[m * NDOWN + 2048 + off];
    float4 a = ((const float4*)src)[0], bb = ((const float4*)src)[1];
    float t[8] = {a.x, a.y, a.z, a.w, bb.x, bb.y, bb.z, bb.w};
    __align__(16) __half hh[8];
#pragma unroll
    for (int pi = 0; pi < 4; pi++) {
        int p = c8*4 + pi;
        float inv = powf(10000.f, (-2.0f * (float)p) / 64.f);
        float sn, cs;
        sincosf((float)s * inv, &sn, &cs);
        float x1 = t[2*pi], x2 = t[2*pi+1];
        hh[2*pi]   = __float2half(x1 * cs - x2 * sn);
        hh[2*pi+1] = __float2half(x1 * sn + x2 * cs);
    }
    *(uint4*)&out[((size_t)bh * SS + s) * 192 + 128 + off] = *(uint4*)hh;
}

// ---------------- pack V transpose ----------------
__global__ __launch_bounds__(256) void pack_v(const __half* __restrict__ kv16,
                                              __half* __restrict__ vt)
{
    __shared__ float vs[64][129];
    const int t = blockIdx.x, h = blockIdx.y, b = blockIdx.z;
    const int bh = b*NH + h;
    const int tid = threadIdx.x;
    for (int i = tid; i < 64*16; i += 256) {
        int r = i >> 4, d8 = (i & 15) * 8;
        size_t m = (size_t)b * SS + t*64 + r;
        uint4 raw = *(const uint4*)&kv16[m * (NH*256) + h*256 + 128 + d8];
        const __half* hp = (const __half*)&raw;
#pragma unroll
        for (int k = 0; k < 8; k++) vs[r][d8 + k] = __half2float(hp[k]);
    }
    __syncthreads();
    for (int i = tid; i < 128*8; i += 256) {
        int d = i >> 3, w8 = i & 7;
        int kk0 = w8 * 8;
        __align__(16) __half p[8];
#pragma unroll
        for (int k = 0; k < 8; k++) p[k] = __float2half(vs[kk0 + k][d]);
        *(uint4*)&vt[((size_t)bh * 128 + d) * SS + t*64 + kk0] = *(uint4*)p;
    }
}

// ============================================================
// HMMA flash attention — R15 core (verified at 669us)
// ============================================================
#define KBASE 49152u
#define VBASE 73728u
#define PBASE 90112u
#define ATT_SMEM 108544

__global__ __launch_bounds__(256, 2) void attn_mma(
    const __half* __restrict__ Qsp, const __half* __restrict__ Ksp,
    const __half* __restrict__ Vt, __half* __restrict__ ats)
{
    extern __shared__ __align__(16) char smem[];
    const uint32_t sb = smem_u32(smem);
    const int qt = (int)gridDim.x - 1 - (int)blockIdx.x;
    const int h = blockIdx.y, b = blockIdx.z;
    const int bh = b*NH + h;
    const int q0 = qt * 64;
    const int tid = threadIdx.x, lane = tid & 31;
    const int wm = (tid >> 5) & 3, wn = tid >> 7;

    const __half* Qg = Qsp + ((size_t)bh * SS + q0) * 384;
    const __half* Kg = Ksp + (size_t)bh * SS * 192;
    const __half* Vg = Vt  + (size_t)bh * 128 * SS;

    float* redmax = (float*)(smem + 107520);
    float* redsum = (float*)(smem + 108032);

    {
        int r = tid >> 3, ch = tid & 7;
#pragma unroll
        for (int cq = 0; cq < 6; cq++) {
#pragma unroll
            for (int it = 0; it < 2; it++) {
                int rr = r + it*32;
                CPA16(sb + (uint32_t)cq*8192u + sw128(rr, ch),
                      Qg + (size_t)rr*384 + cq*64 + ch*8);
            }
        }
        CPCOMMIT();
    }

    float acc_o[8][4];
#pragma unroll
    for (int i = 0; i < 8; i++)
#pragma unroll
        for (int j = 0; j < 4; j++) acc_o[i][j] = 0.f;
    float m0 = -1e30f, m1 = -1e30f, l0 = 0.f, l1 = 0.f;

    const int a_row  = lane & 15;
    const int a_ch   = lane >> 4;
    const int b_nrow = (lane & 7) + ((lane & 16) ? 8 : 0);
    const int b_ch   = (lane >> 3) & 1;
    const int r0 = wm*16 + (lane >> 2);

    for (int t = 0; t <= qt; t++) {
        const int k0 = t * 64;
        {
            int r = tid >> 3, ch = tid & 7;
#pragma unroll
            for (int slot = 0; slot < 2; slot++) {
#pragma unroll
                for (int it = 0; it < 2; it++) {
                    int rr = r + it*32;
                    CPA16(sb + KBASE + (uint32_t)slot*8192u + sw128(rr, ch),
                          Kg + (size_t)(k0 + rr)*192 + slot*64 + ch*8);
                }
                CPCOMMIT();
            }
#pragma unroll
            for (int it = 0; it < 4; it++) {
                int i = tid + it*256;
                int d = i >> 3, vch = i & 7;
                CPA16(sb + VBASE + sw128(d, vch), Vg + (size_t)d*SS + t*64 + vch*8);
            }
            CPCOMMIT();
        }

        float acc_s[4][4];
#pragma unroll
        for (int i = 0; i < 4; i++)
#pragma unroll
            for (int j = 0; j < 4; j++) acc_s[i][j] = 0.f;

#pragma unroll
        for (int c = 0; c < 3; c++) {
            if (c < 2) { CPWAIT(2); } else { CPWAIT(0); }
            __syncthreads();
            if (c == 0) {
                int r = tid >> 3, ch = tid & 7;
#pragma unroll
                for (int it = 0; it < 2; it++) {
                    int rr = r + it*32;
                    CPA16(sb + KBASE + 2u*8192u + sw128(rr, ch),
                          Kg + (size_t)(k0 + rr)*192 + 2*64 + ch*8);
                }
                CPCOMMIT();
            }
            uint32_t kb = sb + KBASE + (uint32_t)c*8192u;
            uint32_t qh = sb + (uint32_t)c*8192u;
            uint32_t ql = sb + (uint32_t)(c+3)*8192u;
#pragma unroll
            for (int ks = 0; ks < 4; ks++) {
                uint32_t a0[4], a1[4];
                ldsm4(a0, qh + sw128(wm*16 + a_row, ks*2 + a_ch));
                ldsm4(a1, ql + sw128(wm*16 + a_row, ks*2 + a_ch));
#pragma unroll
                for (int g = 0; g < 2; g++) {
                    uint32_t bb[4];
                    ldsm4(bb, kb + sw128(wn*32 + g*16 + b_nrow, ks*2 + b_ch));
                    mma16816(acc_s[g*2],   a0, bb[0], bb[1]);
                    mma16816(acc_s[g*2+1], a0, bb[2], bb[3]);
                    mma16816(acc_s[g*2],   a1, bb[0], bb[1]);
                    mma16816(acc_s[g*2+1], a1, bb[2], bb[3]);
                }
            }
        }

        if (t == qt) {
#pragma unroll
            for (int nt = 0; nt < 4; nt++) {
                int colb = wn*32 + nt*8 + (lane & 3)*2;
                if (colb     > r0)     acc_s[nt][0] = -1e30f;
                if (colb + 1 > r0)     acc_s[nt][1] = -1e30f;
                if (colb     > r0 + 8) acc_s[nt][2] = -1e30f;
                if (colb + 1 > r0 + 8) acc_s[nt][3] = -1e30f;
            }
        }

        float mx0 = -1e30f, mx1 = -1e30f;
#pragma unroll
        for (int nt = 0; nt < 4; nt++) {
            mx0 = fmaxf(mx0, fmaxf(acc_s[nt][0], acc_s[nt][1]));
            mx1 = fmaxf(mx1, fmaxf(acc_s[nt][2], acc_s[nt][3]));
        }
        mx0 = fmaxf(mx0, __shfl_xor_sync(0xffffffffu, mx0, 1));
        mx0 = fmaxf(mx0, __shfl_xor_sync(0xffffffffu, mx0, 2));
        mx1 = fmaxf(mx1, __shfl_xor_sync(0xffffffffu, mx1, 1));
        mx1 = fmaxf(mx1, __shfl_xor_sync(0xffffffffu, mx1, 2));
        if ((lane & 3) == 0) {
            redmax[wn*64 + r0]     = mx0;
            redmax[wn*64 + r0 + 8] = mx1;
        }
        __syncthreads();
        float tm0 = fmaxf(mx0, redmax[(wn^1)*64 + r0]);
        float tm1 = fmaxf(mx1, redmax[(wn^1)*64 + r0 + 8]);
        float nm0 = fmaxf(m0, tm0), nm1 = fmaxf(m1, tm1);
        float f0 = __expf(m0 - nm0), f1 = __expf(m1 - nm1);

        float s0 = 0.f, s1 = 0.f;
#pragma unroll
        for (int nt = 0; nt < 4; nt++) {
            acc_s[nt][0] = __expf(acc_s[nt][0] - nm0);
            acc_s[nt][1] = __expf(acc_s[nt][1] - nm0);
            acc_s[nt][2] = __expf(acc_s[nt][2] - nm1);
            acc_s[nt][3] = __expf(acc_s[nt][3] - nm1);
            s0 += acc_s[nt][0] + acc_s[nt][1];
            s1 += acc_s[nt][2] + acc_s[nt][3];
        }
        s0 += __shfl_xor_sync(0xffffffffu, s0, 1);
        s0 += __shfl_xor_sync(0xffffffffu, s0, 2);
        s1 += __shfl_xor_sync(0xffffffffu, s1, 1);
        s1 += __shfl_xor_sync(0xffffffffu, s1, 2);
        if ((lane & 3) == 0) {
            redsum[wn*64 + r0]     = s0;
            redsum[wn*64 + r0 + 8] = s1;
        }
        {
            char* P = smem + PBASE;
            int colb = wn*32 + (lane & 3)*2;
#pragma unroll
            for (int nt = 0; nt < 4; nt++) {
                int col = colb + nt*8;
#pragma unroll
                for (int half = 0; half < 2; half++) {
                    int row = r0 + half*8;
                    *(uint32_t*)(P + row*272 + col*2) =
                        pack2h(acc_s[nt][half*2], acc_s[nt][half*2+1]);
                }
            }
        }
        __syncthreads();
        float ts0 = s0 + redsum[(wn^1)*64 + r0];
        float ts1 = s1 + redsum[(wn^1)*64 + r0 + 8];
        l0 = l0 * f0 + ts0;
        l1 = l1 * f1 + ts1;
        m0 = nm0; m1 = nm1;
#pragma unroll
        for (int nt = 0; nt < 8; nt++) {
            acc_o[nt][0] *= f0; acc_o[nt][1] *= f0;
            acc_o[nt][2] *= f1; acc_o[nt][3] *= f1;
        }

#pragma unroll
        for (int ks = 0; ks < 4; ks++) {
            uint32_t a[4];
            ldsm4(a, sb + PBASE + (uint32_t)((wm*16 + a_row)*272)
                     + (uint32_t)(ks*32 + a_ch*16));
#pragma unroll
            for (int g = 0; g < 4; g++) {
                uint32_t bb[4];
                ldsm4(bb, sb + VBASE + sw128(wn*64 + g*16 + b_nrow, ks*2 + b_ch));
                mma16816(acc_o[g*2],   a, bb[0], bb[1]);
                mma16816(acc_o[g*2+1], a, bb[2], bb[3]);
            }
        }
        __syncthreads();
    }

    float il0 = 1.f / l0, il1 = 1.f / l1;
    size_t mrow0 = (size_t)b * SS + q0 + r0;
#pragma unroll
    for (int nt = 0; nt < 8; nt++) {
        int col = h*128 + wn*64 + nt*8 + (lane & 3)*2;
#pragma unroll
        for (int half = 0; half < 2; half++) {
            float oa = acc_o[nt][half*2]   * (half ? il1 : il0);
            float ob = acc_o[nt][half*2+1] * (half ? il1 : il0);
            size_t row = mrow0 + half*8;
            ((uint32_t*)(ats + row * 2048))[col >> 1] = pack2h(oa, ob);
        }
    }
}

// ---------------- host orchestration ----------------
extern "C" void kernel_launch(void* const* d_in, const int* in_sizes, int n_in,
                              void* d_out, int out_size)
{
    const float* x        = (const float*)d_in[0];
    const float* wq_down  = (const float*)d_in[1];
    const float* q_norm_w = (const float*)d_in[2];
    const float* wq_up    = (const float*)d_in[3];
    const float* wq_rope  = (const float*)d_in[4];
    const float* wkv_down = (const float*)d_in[5];
    const float* kv_norm_w= (const float*)d_in[6];
    const float* wkv_up   = (const float*)d_in[7];
    const float* wk_rope  = (const float*)d_in[8];
    const float* wo       = (const float*)d_in[9];
    float* out = (float*)d_out;

    float* dall;
    cudaGetSymbolAddress((void**)&dall, g_dall);

    __half *xs, *wdall, *qcs, *wuall, *kvcs, *wkvu, *kvu16, *ats, *wos, *qsp, *ksp, *vt;
    cudaGetSymbolAddress((void**)&xs,    g_xs);
    cudaGetSymbolAddress((void**)&wdall, g_wdall);
    cudaGetSymbolAddress((void**)&qcs,   g_qcs);
    cudaGetSymbolAddress((void**)&wuall, g_wuall);
    cudaGetSymbolAddress((void**)&kvcs,  g_kvcs);
    cudaGetSymbolAddress((void**)&wkvu,  g_wkvu);
    cudaGetSymbolAddress((void**)&kvu16, g_kvu16);
    cudaGetSymbolAddress((void**)&ats,   g_ats);
    cudaGetSymbolAddress((void**)&wos,   g_wos);
    cudaGetSymbolAddress((void**)&qsp,   g_qsp);
    cudaGetSymbolAddress((void**)&ksp,   g_ksp);
    cudaGetSymbolAddress((void**)&vt,    g_vt);

    cudaFuncSetAttribute(gemm_f32, cudaFuncAttributeMaxDynamicSharedMemorySize, GEMM_SMEM);
    cudaFuncSetAttribute(gemm_qkv, cudaFuncAttributeMaxDynamicSharedMemorySize, GEMM_SMEM);
    cudaFuncSetAttribute(attn_mma, cudaFuncAttributeMaxDynamicSharedMemorySize, ATT_SMEM);

    // 1. all conversions in one launch
    {
        long long tot = CVT_N4;
        cvt_all<<<(int)((tot + 255) / 256), 256>>>(
            x, wq_down, wkv_down, wk_rope, wq_up, wq_rope, wkv_up, wo,
            xs, wdall, wuall, wkvu, wos);
    }

    // 2. down projection
    gemm_f32<<<dim3((NDOWN + 127)/128, MT/128), 256, GEMM_SMEM>>>(xs, wdall, dall, MT, NDOWN, DIMM);

    // 3. merged rmsnorm -> fp16 hi
    rmsnorm2_k<<<dim3(MT, 2), 256>>>(dall, q_norm_w, kv_norm_w, qcs, kvcs);

    // 4. merged up projections (fused epilogues), heavy CTAs first
    gemm_qkv<<<QP_BLOCKS + KV_BLOCKS, 256, GEMM_SMEM>>>(qcs, wuall, kvcs, wkvu, qsp, kvu16, ksp);

    // 5. kr rope + pack
    {
        long long tot = (long long)BB*NH*SS*8;
        rope_pack_kr<<<(int)((tot + 255) / 256), 256>>>(dall, ksp);
    }

    // 6. V transpose pack
    pack_v<<<dim3(SS/64, NH, BB), 256>>>(kvu16, vt);

    // 7. attention
    attn_mma<<<dim3(SS/64, NH, BB), 256, ATT_SMEM>>>(qsp, ksp, vt, ats);

    // 8. output projection
    gemm_f32<<<dim3((DIMM + 127)/128, MT/128), 256, GEMM_SMEM>>>(ats, wos, out, MT, DIMM, NH*DVV);
}